// round 1
// baseline (speedup 1.0000x reference)
#include <cuda_runtime.h>
#include <math.h>

// Problem constants
constexpr int Bn = 4;
constexpr int Sn = 2048;
constexpr int Dn = 1024;
constexpr int Hn = 16;
constexpr int DKn = 64;      // head dim
constexpr int Mn = Bn * Sn;  // 8192 rows

// Scratch (static device arrays — no allocation allowed)
__device__ float g_Q[Bn * Hn * Sn * DKn];     // [b,h,s,dk]
__device__ float g_K[Bn * Hn * Sn * DKn];
__device__ float g_V[Bn * Hn * Sn * DKn];
__device__ float g_attn[Bn * Sn * Dn];        // [b,s,d]
__device__ float g_cos[Sn * 32];
__device__ float g_sin[Sn * 32];

// ---------------------------------------------------------------------------
// RoPE table: cos/sin per (position, freq)
// ---------------------------------------------------------------------------
__global__ void rope_tab_kernel(const int* __restrict__ pos) {
    int idx = blockIdx.x * 256 + threadIdx.x;
    if (idx >= Sn * 32) return;
    int s = idx >> 5;
    int f = idx & 31;
    // inv_freq = 10000^(-(2f)/64) = exp(-f/32 * ln(10000))
    float inv = expf(-(float)f * (logf(10000.0f) / 32.0f));
    float a = (float)pos[s] * inv;
    g_cos[idx] = cosf(a);
    g_sin[idx] = sinf(a);
}

// ---------------------------------------------------------------------------
// GEMM: out = A[8192,1024] @ W[1024,1024]
// Tile 128x128x8, 256 threads, 8x8 microtile.
// MODE 0: RoPE + head-major store  (Q, K)
// MODE 1: head-major store          (V)
// MODE 2: row-major store           (out-proj, to d_out)
// Thread column mapping: cols = n0 + tx*4 + {0..3}  and  n0 + 64 + tx*4 + {0..3}
// (two contiguous float4 groups -> conflict-free LDS.128)
// ---------------------------------------------------------------------------
template <int MODE>
__global__ __launch_bounds__(256, 2) void gemm128_kernel(
    const float* __restrict__ A, const float* __restrict__ W,
    float* __restrict__ out) {
    __shared__ float As[8][132];   // [k][m], padded
    __shared__ float Bs[8][128];   // [k][n]

    const int tid = threadIdx.x;
    const int tx = tid & 15;       // 0..15
    const int ty = tid >> 4;       // 0..15
    const int m0 = blockIdx.y * 128;
    const int n0 = blockIdx.x * 128;

    float acc[8][8];
#pragma unroll
    for (int i = 0; i < 8; ++i)
#pragma unroll
        for (int j = 0; j < 8; ++j) acc[i][j] = 0.0f;

    const int am = tid >> 1;             // 0..127 row within tile
    const int akv = (tid & 1) * 4;       // 0 or 4
    const int bkr = tid >> 5;            // 0..7
    const int bc4 = (tid & 31) * 4;      // 0..124

    for (int k0 = 0; k0 < Dn; k0 += 8) {
        // Load A tile (transposed into smem) and B tile
        float4 av = *(const float4*)(A + (size_t)(m0 + am) * Dn + k0 + akv);
        As[akv + 0][am] = av.x;
        As[akv + 1][am] = av.y;
        As[akv + 2][am] = av.z;
        As[akv + 3][am] = av.w;
        *(float4*)&Bs[bkr][bc4] =
            *(const float4*)(W + (size_t)(k0 + bkr) * Dn + n0 + bc4);
        __syncthreads();

#pragma unroll
        for (int kk = 0; kk < 8; ++kk) {
            float a[8], b[8];
            *(float4*)&a[0] = *(const float4*)&As[kk][ty * 8];
            *(float4*)&a[4] = *(const float4*)&As[kk][ty * 8 + 4];
            *(float4*)&b[0] = *(const float4*)&Bs[kk][tx * 4];
            *(float4*)&b[4] = *(const float4*)&Bs[kk][64 + tx * 4];
#pragma unroll
            for (int i = 0; i < 8; ++i)
#pragma unroll
                for (int j = 0; j < 8; ++j) acc[i][j] += a[i] * b[j];
        }
        __syncthreads();
    }

    // Epilogue
    const int row_base = m0 + ty * 8;
#pragma unroll
    for (int i = 0; i < 8; ++i) {
        const int grow = row_base + i;          // b*S + s
        if (MODE == 2) {
            *(float4*)&out[(size_t)grow * Dn + n0 + tx * 4] =
                make_float4(acc[i][0], acc[i][1], acc[i][2], acc[i][3]);
            *(float4*)&out[(size_t)grow * Dn + n0 + 64 + tx * 4] =
                make_float4(acc[i][4], acc[i][5], acc[i][6], acc[i][7]);
        } else {
            const int b_ = grow >> 11;          // / Sn
            const int s_ = grow & (Sn - 1);
            const int h0 = n0 >> 6;
#pragma unroll
            for (int half = 0; half < 2; ++half) {
                const int h = h0 + half;
                float e0 = acc[i][half * 4 + 0];
                float e1 = acc[i][half * 4 + 1];
                float e2 = acc[i][half * 4 + 2];
                float e3 = acc[i][half * 4 + 3];
                if (MODE == 0) {
                    const int f0 = tx * 2, f1 = tx * 2 + 1;
                    const float c0 = g_cos[s_ * 32 + f0], sn0 = g_sin[s_ * 32 + f0];
                    const float c1 = g_cos[s_ * 32 + f1], sn1 = g_sin[s_ * 32 + f1];
                    float r0 = e0 * c0 - e1 * sn0;
                    float r1 = e0 * sn0 + e1 * c0;
                    float r2 = e2 * c1 - e3 * sn1;
                    float r3 = e2 * sn1 + e3 * c1;
                    e0 = r0; e1 = r1; e2 = r2; e3 = r3;
                }
                *(float4*)&out[(((size_t)b_ * Hn + h) * Sn + s_) * DKn + tx * 4] =
                    make_float4(e0, e1, e2, e3);
            }
        }
    }
}

// ---------------------------------------------------------------------------
// Flash attention (fp32, causal). One block = 64 queries of one (b,h).
// 256 threads as (ty,tx)=(16,16); 4x4 microtile on the 64x64 score tile.
// ---------------------------------------------------------------------------
__global__ __launch_bounds__(256, 3) void attn_kernel(
    const float* __restrict__ Q, const float* __restrict__ K,
    const float* __restrict__ V, float* __restrict__ Ow) {
    __shared__ float Qt[64][68];   // [d][q]
    __shared__ float Kt[64][68];   // [d][k]
    __shared__ float Pt[64][68];   // [k][q]
    __shared__ float Vs[64][64];   // [k][d]

    const int tid = threadIdx.x;
    const int tx = tid & 15;
    const int ty = tid >> 4;
    const int bh = blockIdx.y;               // b*H + h
    const int q0 = blockIdx.x * 64;

    const float* Qb = Q + ((size_t)bh * Sn + q0) * DKn;
    const float* Kb = K + (size_t)bh * Sn * DKn;
    const float* Vb = V + (size_t)bh * Sn * DKn;

    // Load Q tile transposed
    for (int v = tid; v < 64 * 16; v += 256) {
        int r = v >> 4;
        int d4 = (v & 15) * 4;
        float4 q4 = *(const float4*)(Qb + r * DKn + d4);
        Qt[d4 + 0][r] = q4.x;
        Qt[d4 + 1][r] = q4.y;
        Qt[d4 + 2][r] = q4.z;
        Qt[d4 + 3][r] = q4.w;
    }

    float m_[4], l_[4], o_[4][4];
#pragma unroll
    for (int i = 0; i < 4; ++i) {
        m_[i] = -INFINITY;
        l_[i] = 0.0f;
#pragma unroll
        for (int j = 0; j < 4; ++j) o_[i][j] = 0.0f;
    }
    __syncthreads();

    const int qtile = blockIdx.x;
    for (int kt = 0; kt <= qtile; ++kt) {
        const float* Kp = Kb + (size_t)kt * 64 * DKn;
        const float* Vp = Vb + (size_t)kt * 64 * DKn;
        for (int v = tid; v < 1024; v += 256) {
            int r = v >> 4;
            int d4 = (v & 15) * 4;
            float4 k4 = *(const float4*)(Kp + r * DKn + d4);
            Kt[d4 + 0][r] = k4.x;
            Kt[d4 + 1][r] = k4.y;
            Kt[d4 + 2][r] = k4.z;
            Kt[d4 + 3][r] = k4.w;
            *(float4*)&Vs[r][d4] = *(const float4*)(Vp + r * DKn + d4);
        }
        __syncthreads();

        // scores = Q . K^T
        float sc[4][4];
#pragma unroll
        for (int i = 0; i < 4; ++i)
#pragma unroll
            for (int j = 0; j < 4; ++j) sc[i][j] = 0.0f;

#pragma unroll 8
        for (int d = 0; d < 64; ++d) {
            float4 qa = *(const float4*)&Qt[d][ty * 4];
            float4 ka = *(const float4*)&Kt[d][tx * 4];
            float qv[4] = {qa.x, qa.y, qa.z, qa.w};
            float kv[4] = {ka.x, ka.y, ka.z, ka.w};
#pragma unroll
            for (int i = 0; i < 4; ++i)
#pragma unroll
                for (int j = 0; j < 4; ++j) sc[i][j] += qv[i] * kv[j];
        }

        const float scale = 0.125f;  // 1/sqrt(64)
        if (kt == qtile) {
#pragma unroll
            for (int i = 0; i < 4; ++i) {
                const int qr = q0 + ty * 4 + i;
#pragma unroll
                for (int j = 0; j < 4; ++j) {
                    const int kc = kt * 64 + tx * 4 + j;
                    sc[i][j] = (kc <= qr) ? sc[i][j] * scale : -INFINITY;
                }
            }
        } else {
#pragma unroll
            for (int i = 0; i < 4; ++i)
#pragma unroll
                for (int j = 0; j < 4; ++j) sc[i][j] *= scale;
        }

        // online softmax (row reductions across the 16 tx lanes)
#pragma unroll
        for (int i = 0; i < 4; ++i) {
            float rm = fmaxf(fmaxf(sc[i][0], sc[i][1]), fmaxf(sc[i][2], sc[i][3]));
#pragma unroll
            for (int off = 8; off >= 1; off >>= 1)
                rm = fmaxf(rm, __shfl_xor_sync(0xffffffffu, rm, off, 16));
            const float nm = fmaxf(m_[i], rm);
            const float corr = __expf(m_[i] - nm);
            float rs = 0.0f;
#pragma unroll
            for (int j = 0; j < 4; ++j) {
                float p = __expf(sc[i][j] - nm);
                sc[i][j] = p;
                rs += p;
            }
#pragma unroll
            for (int off = 8; off >= 1; off >>= 1)
                rs += __shfl_xor_sync(0xffffffffu, rs, off, 16);
            l_[i] = l_[i] * corr + rs;
            m_[i] = nm;
#pragma unroll
            for (int j = 0; j < 4; ++j) o_[i][j] *= corr;
        }

        // write P transposed
#pragma unroll
        for (int j = 0; j < 4; ++j)
#pragma unroll
            for (int i = 0; i < 4; ++i) Pt[tx * 4 + j][ty * 4 + i] = sc[i][j];
        __syncthreads();

        // O += P . V
#pragma unroll 8
        for (int d = 0; d < 64; ++d) {
            float4 pa = *(const float4*)&Pt[d][ty * 4];
            float4 va = *(const float4*)&Vs[d][tx * 4];
            float pv[4] = {pa.x, pa.y, pa.z, pa.w};
            float vv[4] = {va.x, va.y, va.z, va.w};
#pragma unroll
            for (int i = 0; i < 4; ++i)
#pragma unroll
                for (int j = 0; j < 4; ++j) o_[i][j] += pv[i] * vv[j];
        }
        __syncthreads();
    }

    // write out: [b, s, h*64 + dk]
    const int b_ = bh >> 4;
    const int h = bh & 15;
#pragma unroll
    for (int i = 0; i < 4; ++i) {
        const int qr = q0 + ty * 4 + i;
        const float inv_l = 1.0f / l_[i];
        *(float4*)&Ow[((size_t)b_ * Sn + qr) * Dn + h * DKn + tx * 4] =
            make_float4(o_[i][0] * inv_l, o_[i][1] * inv_l,
                        o_[i][2] * inv_l, o_[i][3] * inv_l);
    }
}

// ---------------------------------------------------------------------------
extern "C" void kernel_launch(void* const* d_in, const int* in_sizes, int n_in,
                              void* d_out, int out_size) {
    const float* x  = (const float*)d_in[0];
    const float* Wq = (const float*)d_in[1];
    const float* Wk = (const float*)d_in[2];
    const float* Wv = (const float*)d_in[3];
    const float* Wo = (const float*)d_in[4];
    const int* pos  = (const int*)d_in[5];
    float* out = (float*)d_out;

    float *pQ, *pK, *pV, *pA;
    cudaGetSymbolAddress((void**)&pQ, g_Q);
    cudaGetSymbolAddress((void**)&pK, g_K);
    cudaGetSymbolAddress((void**)&pV, g_V);
    cudaGetSymbolAddress((void**)&pA, g_attn);

    rope_tab_kernel<<<(Sn * 32 + 255) / 256, 256>>>(pos);

    dim3 ggrid(Dn / 128, Mn / 128);  // (8, 64)
    gemm128_kernel<0><<<ggrid, 256>>>(x, Wq, pQ);
    gemm128_kernel<0><<<ggrid, 256>>>(x, Wk, pK);
    gemm128_kernel<1><<<ggrid, 256>>>(x, Wv, pV);

    dim3 agrid(Sn / 64, Bn * Hn);    // (32, 64)
    attn_kernel<<<agrid, 256>>>(pQ, pK, pV, pA);

    gemm128_kernel<2><<<ggrid, 256>>>(pA, Wo, out);
}

// round 3
// speedup vs baseline: 1.4420x; 1.4420x over previous
#include <cuda_runtime.h>
#include <cuda_bf16.h>
#include <math.h>
#include <cstdint>

// Problem constants
constexpr int Bn = 4;
constexpr int Sn = 2048;
constexpr int Dn = 1024;
constexpr int Hn = 16;
constexpr int DKn = 64;
constexpr int Mn = Bn * Sn;  // 8192

// ---------------------------------------------------------------------------
// Scratch (static device arrays — no allocation allowed)
// ---------------------------------------------------------------------------
__device__ __nv_bfloat16 g_xh[Mn * Dn];        // x split hi (bf16)
__device__ __nv_bfloat16 g_xl[Mn * Dn];        // x split lo
__device__ __nv_bfloat16 g_Wh[4 * Dn * Dn];    // W^T split hi (4 weights, [n][k])
__device__ __nv_bfloat16 g_Wl[4 * Dn * Dn];    // W^T split lo
__device__ float g_Q[Mn * Dn];                 // [b,h,s,dk] fp32
__device__ float g_K[Mn * Dn];
__device__ float g_V[Mn * Dn];
__device__ __nv_bfloat16 g_ah[Mn * Dn];        // attn out hi [b,s,d]
__device__ __nv_bfloat16 g_al[Mn * Dn];        // attn out lo
__device__ float g_cos[Sn * 32];
__device__ float g_sin[Sn * 32];

// ---------------------------------------------------------------------------
// PTX helpers (base sm_103 target only: cp.async / ldmatrix / mma.sync)
// ---------------------------------------------------------------------------
__device__ __forceinline__ uint32_t s2u(const void* p) {
    uint32_t a;
    asm("{ .reg .u64 t; cvta.to.shared.u64 t, %1; cvt.u32.u64 %0, t; }"
        : "=r"(a) : "l"(p));
    return a;
}

__device__ __forceinline__ void cpa16(uint32_t dst, const void* src) {
    asm volatile("cp.async.cg.shared.global [%0], [%1], 16;"
                 :: "r"(dst), "l"(src) : "memory");
}
#define CP_COMMIT() asm volatile("cp.async.commit_group;" ::: "memory")
#define CP_WAIT1() asm volatile("cp.async.wait_group 1;" ::: "memory")
#define CP_WAIT0() asm volatile("cp.async.wait_group 0;" ::: "memory")

__device__ __forceinline__ void ldsm4(uint32_t addr, uint32_t* r) {
    asm volatile(
        "ldmatrix.sync.aligned.m8n8.x4.shared.b16 {%0,%1,%2,%3}, [%4];"
        : "=r"(r[0]), "=r"(r[1]), "=r"(r[2]), "=r"(r[3]) : "r"(addr));
}

__device__ __forceinline__ void mma_bf16(float* c, const uint32_t* a,
                                         uint32_t b0, uint32_t b1) {
    asm volatile(
        "mma.sync.aligned.m16n8k16.row.col.f32.bf16.bf16.f32 "
        "{%0,%1,%2,%3}, {%4,%5,%6,%7}, {%8,%9}, {%0,%1,%2,%3};"
        : "+f"(c[0]), "+f"(c[1]), "+f"(c[2]), "+f"(c[3])
        : "r"(a[0]), "r"(a[1]), "r"(a[2]), "r"(a[3]), "r"(b0), "r"(b1));
}

// ---------------------------------------------------------------------------
// Prep kernels
// ---------------------------------------------------------------------------
__global__ void rope_tab_kernel(const int* __restrict__ pos) {
    int idx = blockIdx.x * 256 + threadIdx.x;
    if (idx >= Sn * 32) return;
    int s = idx >> 5;
    int f = idx & 31;
    float inv = expf(-(float)f * (logf(10000.0f) / 32.0f));
    float a = (float)pos[s] * inv;
    g_cos[idx] = cosf(a);
    g_sin[idx] = sinf(a);
}

__global__ void split_x_kernel(const float* __restrict__ x,
                               __nv_bfloat16* __restrict__ xh,
                               __nv_bfloat16* __restrict__ xl) {
    size_t i = ((size_t)blockIdx.x * 256 + threadIdx.x) * 4;
    float4 a = *(const float4*)(x + i);
    float v[4] = {a.x, a.y, a.z, a.w};
    __nv_bfloat162 h2[2], l2[2];
#pragma unroll
    for (int p = 0; p < 2; ++p) {
        __nv_bfloat16 h0 = __float2bfloat16(v[2 * p]);
        __nv_bfloat16 h1 = __float2bfloat16(v[2 * p + 1]);
        h2[p] = __nv_bfloat162(h0, h1);
        l2[p] = __nv_bfloat162(
            __float2bfloat16(v[2 * p] - __bfloat162float(h0)),
            __float2bfloat16(v[2 * p + 1] - __bfloat162float(h1)));
    }
    *(uint2*)(xh + i) = *(uint2*)h2;
    *(uint2*)(xl + i) = *(uint2*)l2;
}

// W[k][n] -> WT[n][k] bf16 split
__global__ void transpose_split_kernel(const float* __restrict__ W,
                                       __nv_bfloat16* __restrict__ Th,
                                       __nv_bfloat16* __restrict__ Tl) {
    __shared__ float t[32][33];
    int n0 = blockIdx.x * 32, k0 = blockIdx.y * 32;
    int tx = threadIdx.x;
#pragma unroll
    for (int i = threadIdx.y; i < 32; i += 8)
        t[i][tx] = W[(size_t)(k0 + i) * Dn + n0 + tx];
    __syncthreads();
#pragma unroll
    for (int i = threadIdx.y; i < 32; i += 8) {
        float a = t[tx][i];  // = W[k0+tx][n0+i]
        __nv_bfloat16 hi = __float2bfloat16(a);
        float lo = a - __bfloat162float(hi);
        Th[(size_t)(n0 + i) * Dn + k0 + tx] = hi;
        Tl[(size_t)(n0 + i) * Dn + k0 + tx] = __float2bfloat16(lo);
    }
}

// ---------------------------------------------------------------------------
// Tensor-core GEMM (mma.sync bf16, 3-pass split):
//   out[8192, 1024] = A @ B   with B supplied as [n][k] (W^T)
// CTA 128x128, K-chunk 32, 2-stage cp.async pipeline.
// 8 warps = 4(M) x 2(N); warp tile 32x64 -> 2 m16-frags x 8 n8-frags.
// MODE 0: RoPE + head-major store (Q,K); MODE 1: head-major (V);
// MODE 2: row-major store (final output).
// ---------------------------------------------------------------------------
constexpr int TM = 128, TN = 128, TK = 32;
constexpr int NCHUNK = Dn / TK;       // 32
constexpr int ROWB = 80;              // padded row stride (bytes) for 32 bf16
constexpr int PLANE = 128 * ROWB;     // 10240 bytes per plane
constexpr int STAGE = 4 * PLANE;      // A_hi, A_lo, B_hi, B_lo = 40960
constexpr int GEMM_SMEM = 2 * STAGE;  // 81920

__device__ __forceinline__ void load_stage(
    uint32_t stb, const __nv_bfloat16* __restrict__ Ah,
    const __nv_bfloat16* __restrict__ Al, const __nv_bfloat16* __restrict__ Bh,
    const __nv_bfloat16* __restrict__ Bl, int m0, int n0, int k0, int tid) {
#pragma unroll
    for (int i = 0; i < 8; ++i) {
        int op = tid + i * 256;
        int plane = op >> 9;        // 0..3
        int w = op & 511;
        int r = w >> 2, ch = w & 3; // row, 16B-chunk
        uint32_t dst = stb + plane * PLANE + r * ROWB + ch * 16;
        const __nv_bfloat16* src;
        if (plane == 0)      src = Ah + (size_t)(m0 + r) * Dn + k0 + ch * 8;
        else if (plane == 1) src = Al + (size_t)(m0 + r) * Dn + k0 + ch * 8;
        else if (plane == 2) src = Bh + (size_t)(n0 + r) * Dn + k0 + ch * 8;
        else                 src = Bl + (size_t)(n0 + r) * Dn + k0 + ch * 8;
        cpa16(dst, src);
    }
}

template <int MODE>
__global__ __launch_bounds__(256) void gemm_mma_kernel(
    const __nv_bfloat16* __restrict__ Ah, const __nv_bfloat16* __restrict__ Al,
    const __nv_bfloat16* __restrict__ Bh, const __nv_bfloat16* __restrict__ Bl,
    float* __restrict__ out) {
    extern __shared__ char smem[];
    const uint32_t sb = s2u(smem);
    const int tid = threadIdx.x;
    const int wid = tid >> 5, lane = tid & 31;
    const int warp_m = wid & 3, warp_n = wid >> 2;
    const int m0 = blockIdx.y * TM, n0 = blockIdx.x * TN;

    float acc[2][8][4];
#pragma unroll
    for (int mf = 0; mf < 2; ++mf)
#pragma unroll
        for (int nf = 0; nf < 8; ++nf)
#pragma unroll
            for (int j = 0; j < 4; ++j) acc[mf][nf][j] = 0.0f;

    // ldmatrix base addresses (lane -> row/byte within tile)
    const int lrow = lane & 15;
    const int lcol = (lane >> 4) * 16;
    const uint32_t aOff = (uint32_t)((warp_m * 32 + lrow) * ROWB + lcol);
    const uint32_t bOff = (uint32_t)(2 * PLANE + (warp_n * 64 + lrow) * ROWB + lcol);

    load_stage(sb, Ah, Al, Bh, Bl, m0, n0, 0, tid);
    CP_COMMIT();

    for (int c = 0; c < NCHUNK; ++c) {
        if (c + 1 < NCHUNK) {
            load_stage(sb + ((c + 1) & 1) * STAGE, Ah, Al, Bh, Bl, m0, n0,
                       (c + 1) * TK, tid);
            CP_COMMIT();
            CP_WAIT1();
        } else {
            CP_WAIT0();
        }
        __syncthreads();

        const uint32_t stb = sb + (c & 1) * STAGE;
#pragma unroll
        for (int ks = 0; ks < 2; ++ks) {
            const uint32_t kb = ks * 32;
            uint32_t ah[2][4], al[2][4];
            ldsm4(stb + aOff + kb, ah[0]);
            ldsm4(stb + aOff + 16 * ROWB + kb, ah[1]);
            ldsm4(stb + PLANE + aOff + kb, al[0]);
            ldsm4(stb + PLANE + aOff + 16 * ROWB + kb, al[1]);
            uint32_t bh[4][4], bl[4][4];
#pragma unroll
            for (int p = 0; p < 4; ++p) {
                ldsm4(stb + bOff + p * 16 * ROWB + kb, bh[p]);
                ldsm4(stb + PLANE + bOff + p * 16 * ROWB + kb, bl[p]);
            }
#pragma unroll
            for (int mf = 0; mf < 2; ++mf)
#pragma unroll
                for (int nf = 0; nf < 8; ++nf) {
                    const int pr = nf >> 1, wh = nf & 1;
                    mma_bf16(acc[mf][nf], ah[mf], bh[pr][wh], bh[pr][2 + wh]);
                    mma_bf16(acc[mf][nf], ah[mf], bl[pr][wh], bl[pr][2 + wh]);
                    mma_bf16(acc[mf][nf], al[mf], bh[pr][wh], bh[pr][2 + wh]);
                }
        }
        __syncthreads();
    }

    // Epilogue
    const int gid = lane >> 2, tig = lane & 3;
#pragma unroll
    for (int mf = 0; mf < 2; ++mf)
#pragma unroll
        for (int nf = 0; nf < 8; ++nf) {
            const float* cc = acc[mf][nf];
            const int row0 = m0 + warp_m * 32 + mf * 16 + gid;
            const int dcol = nf * 8 + tig * 2;
            if (MODE == 2) {
                const int col = n0 + warp_n * 64 + dcol;
                *(float2*)(out + (size_t)row0 * Dn + col) =
                    make_float2(cc[0], cc[1]);
                *(float2*)(out + (size_t)(row0 + 8) * Dn + col) =
                    make_float2(cc[2], cc[3]);
            } else {
                const int h = (n0 + warp_n * 64) >> 6;
#pragma unroll
                for (int rr = 0; rr < 2; ++rr) {
                    const int row = row0 + rr * 8;
                    const int b_ = row >> 11, s_ = row & (Sn - 1);
                    float e0 = cc[rr * 2], e1 = cc[rr * 2 + 1];
                    if (MODE == 0) {
                        const int f = nf * 4 + tig;
                        const float cz = g_cos[s_ * 32 + f];
                        const float sz = g_sin[s_ * 32 + f];
                        const float r1 = e0 * cz - e1 * sz;
                        const float r2 = e0 * sz + e1 * cz;
                        e0 = r1; e1 = r2;
                    }
                    *(float2*)(out + (((size_t)b_ * Hn + h) * Sn + s_) * DKn +
                               dcol) = make_float2(e0, e1);
                }
            }
        }
}

// ---------------------------------------------------------------------------
// Flash attention (fp32, causal) — unchanged math; emits bf16 hi/lo split.
// ---------------------------------------------------------------------------
__global__ __launch_bounds__(256, 3) void attn_kernel(
    const float* __restrict__ Q, const float* __restrict__ K,
    const float* __restrict__ V, __nv_bfloat16* __restrict__ Oh,
    __nv_bfloat16* __restrict__ Ol) {
    __shared__ float Qt[64][68];
    __shared__ float Kt[64][68];
    __shared__ float Pt[64][68];
    __shared__ float Vs[64][64];

    const int tid = threadIdx.x;
    const int tx = tid & 15;
    const int ty = tid >> 4;
    const int bh = blockIdx.y;
    const int q0 = blockIdx.x * 64;

    const float* Qb = Q + ((size_t)bh * Sn + q0) * DKn;
    const float* Kb = K + (size_t)bh * Sn * DKn;
    const float* Vb = V + (size_t)bh * Sn * DKn;

    for (int v = tid; v < 64 * 16; v += 256) {
        int r = v >> 4;
        int d4 = (v & 15) * 4;
        float4 q4 = *(const float4*)(Qb + r * DKn + d4);
        Qt[d4 + 0][r] = q4.x;
        Qt[d4 + 1][r] = q4.y;
        Qt[d4 + 2][r] = q4.z;
        Qt[d4 + 3][r] = q4.w;
    }

    float m_[4], l_[4], o_[4][4];
#pragma unroll
    for (int i = 0; i < 4; ++i) {
        m_[i] = -INFINITY;
        l_[i] = 0.0f;
#pragma unroll
        for (int j = 0; j < 4; ++j) o_[i][j] = 0.0f;
    }
    __syncthreads();

    const int qtile = blockIdx.x;
    for (int kt = 0; kt <= qtile; ++kt) {
        const float* Kp = Kb + (size_t)kt * 64 * DKn;
        const float* Vp = Vb + (size_t)kt * 64 * DKn;
        for (int v = tid; v < 1024; v += 256) {
            int r = v >> 4;
            int d4 = (v & 15) * 4;
            float4 k4 = *(const float4*)(Kp + r * DKn + d4);
            Kt[d4 + 0][r] = k4.x;
            Kt[d4 + 1][r] = k4.y;
            Kt[d4 + 2][r] = k4.z;
            Kt[d4 + 3][r] = k4.w;
            *(float4*)&Vs[r][d4] = *(const float4*)(Vp + r * DKn + d4);
        }
        __syncthreads();

        float sc[4][4];
#pragma unroll
        for (int i = 0; i < 4; ++i)
#pragma unroll
            for (int j = 0; j < 4; ++j) sc[i][j] = 0.0f;

#pragma unroll 8
        for (int d = 0; d < 64; ++d) {
            float4 qa = *(const float4*)&Qt[d][ty * 4];
            float4 ka = *(const float4*)&Kt[d][tx * 4];
            float qv[4] = {qa.x, qa.y, qa.z, qa.w};
            float kv[4] = {ka.x, ka.y, ka.z, ka.w};
#pragma unroll
            for (int i = 0; i < 4; ++i)
#pragma unroll
                for (int j = 0; j < 4; ++j) sc[i][j] += qv[i] * kv[j];
        }

        const float scale = 0.125f;
        if (kt == qtile) {
#pragma unroll
            for (int i = 0; i < 4; ++i) {
                const int qr = q0 + ty * 4 + i;
#pragma unroll
                for (int j = 0; j < 4; ++j) {
                    const int kc = kt * 64 + tx * 4 + j;
                    sc[i][j] = (kc <= qr) ? sc[i][j] * scale : -INFINITY;
                }
            }
        } else {
#pragma unroll
            for (int i = 0; i < 4; ++i)
#pragma unroll
                for (int j = 0; j < 4; ++j) sc[i][j] *= scale;
        }

#pragma unroll
        for (int i = 0; i < 4; ++i) {
            float rm = fmaxf(fmaxf(sc[i][0], sc[i][1]), fmaxf(sc[i][2], sc[i][3]));
#pragma unroll
            for (int off = 8; off >= 1; off >>= 1)
                rm = fmaxf(rm, __shfl_xor_sync(0xffffffffu, rm, off, 16));
            const float nm = fmaxf(m_[i], rm);
            const float corr = __expf(m_[i] - nm);
            float rs = 0.0f;
#pragma unroll
            for (int j = 0; j < 4; ++j) {
                float p = __expf(sc[i][j] - nm);
                sc[i][j] = p;
                rs += p;
            }
#pragma unroll
            for (int off = 8; off >= 1; off >>= 1)
                rs += __shfl_xor_sync(0xffffffffu, rs, off, 16);
            l_[i] = l_[i] * corr + rs;
            m_[i] = nm;
#pragma unroll
            for (int j = 0; j < 4; ++j) o_[i][j] *= corr;
        }

#pragma unroll
        for (int j = 0; j < 4; ++j)
#pragma unroll
            for (int i = 0; i < 4; ++i) Pt[tx * 4 + j][ty * 4 + i] = sc[i][j];
        __syncthreads();

#pragma unroll 8
        for (int d = 0; d < 64; ++d) {
            float4 pa = *(const float4*)&Pt[d][ty * 4];
            float4 va = *(const float4*)&Vs[d][tx * 4];
            float pv[4] = {pa.x, pa.y, pa.z, pa.w};
            float vv[4] = {va.x, va.y, va.z, va.w};
#pragma unroll
            for (int i = 0; i < 4; ++i)
#pragma unroll
                for (int j = 0; j < 4; ++j) o_[i][j] += pv[i] * vv[j];
        }
        __syncthreads();
    }

    const int b_ = bh >> 4;
    const int h = bh & 15;
#pragma unroll
    for (int i = 0; i < 4; ++i) {
        const int qr = q0 + ty * 4 + i;
        const float inv_l = 1.0f / l_[i];
        size_t off = ((size_t)b_ * Sn + qr) * Dn + h * DKn + tx * 4;
        __nv_bfloat162 hv[2], lv[2];
#pragma unroll
        for (int p = 0; p < 2; ++p) {
            float v0 = o_[i][2 * p] * inv_l;
            float v1 = o_[i][2 * p + 1] * inv_l;
            __nv_bfloat16 h0 = __float2bfloat16(v0);
            __nv_bfloat16 h1 = __float2bfloat16(v1);
            hv[p] = __nv_bfloat162(h0, h1);
            lv[p] = __nv_bfloat162(
                __float2bfloat16(v0 - __bfloat162float(h0)),
                __float2bfloat16(v1 - __bfloat162float(h1)));
        }
        *(uint2*)(Oh + off) = *(uint2*)hv;
        *(uint2*)(Ol + off) = *(uint2*)lv;
    }
}

// ---------------------------------------------------------------------------
extern "C" void kernel_launch(void* const* d_in, const int* in_sizes, int n_in,
                              void* d_out, int out_size) {
    const float* x  = (const float*)d_in[0];
    const float* Wq = (const float*)d_in[1];
    const float* Wk = (const float*)d_in[2];
    const float* Wv = (const float*)d_in[3];
    const float* Wo = (const float*)d_in[4];
    const int* pos  = (const int*)d_in[5];
    float* out = (float*)d_out;

    __nv_bfloat16 *pxh, *pxl, *pWh, *pWl, *pah, *pal;
    float *pQ, *pK, *pV;
    cudaGetSymbolAddress((void**)&pxh, g_xh);
    cudaGetSymbolAddress((void**)&pxl, g_xl);
    cudaGetSymbolAddress((void**)&pWh, g_Wh);
    cudaGetSymbolAddress((void**)&pWl, g_Wl);
    cudaGetSymbolAddress((void**)&pQ, g_Q);
    cudaGetSymbolAddress((void**)&pK, g_K);
    cudaGetSymbolAddress((void**)&pV, g_V);
    cudaGetSymbolAddress((void**)&pah, g_ah);
    cudaGetSymbolAddress((void**)&pal, g_al);

    cudaFuncSetAttribute((const void*)gemm_mma_kernel<0>,
                         cudaFuncAttributeMaxDynamicSharedMemorySize, GEMM_SMEM);
    cudaFuncSetAttribute((const void*)gemm_mma_kernel<1>,
                         cudaFuncAttributeMaxDynamicSharedMemorySize, GEMM_SMEM);
    cudaFuncSetAttribute((const void*)gemm_mma_kernel<2>,
                         cudaFuncAttributeMaxDynamicSharedMemorySize, GEMM_SMEM);

    rope_tab_kernel<<<(Sn * 32 + 255) / 256, 256>>>(pos);
    split_x_kernel<<<Mn * Dn / 1024, 256>>>(x, pxh, pxl);
    const float* Ws[4] = {Wq, Wk, Wv, Wo};
    for (int w = 0; w < 4; ++w)
        transpose_split_kernel<<<dim3(32, 32), dim3(32, 8)>>>(
            Ws[w], pWh + (size_t)w * Dn * Dn, pWl + (size_t)w * Dn * Dn);

    dim3 gg(Dn / TN, Mn / TM);  // (8, 64)
    gemm_mma_kernel<0><<<gg, 256, GEMM_SMEM>>>(pxh, pxl, pWh, pWl, pQ);
    gemm_mma_kernel<0><<<gg, 256, GEMM_SMEM>>>(pxh, pxl, pWh + Dn * Dn,
                                               pWl + Dn * Dn, pK);
    gemm_mma_kernel<1><<<gg, 256, GEMM_SMEM>>>(pxh, pxl, pWh + 2 * Dn * Dn,
                                               pWl + 2 * Dn * Dn, pV);

    dim3 agrid(Sn / 64, Bn * Hn);
    attn_kernel<<<agrid, 256>>>(pQ, pK, pV, pah, pal);

    gemm_mma_kernel<2><<<gg, 256, GEMM_SMEM>>>(pah, pal, pWh + 3 * Dn * Dn,
                                               pWl + 3 * Dn * Dn, out);
}

// round 4
// speedup vs baseline: 2.3295x; 1.6154x over previous
#include <cuda_runtime.h>
#include <cuda_bf16.h>
#include <math.h>
#include <cstdint>

// Problem constants
constexpr int Bn = 4;
constexpr int Sn = 2048;
constexpr int Dn = 1024;
constexpr int Hn = 16;
constexpr int DKn = 64;
constexpr int Mn = Bn * Sn;  // 8192

// Q pre-scale: 1/sqrt(64) * log2(e)  (logits kept in log2 units)
#define QSCALE 0.18033688011112042f

// ---------------------------------------------------------------------------
// Scratch (static device arrays — no allocation allowed)
// ---------------------------------------------------------------------------
__device__ __nv_bfloat16 g_xh[Mn * Dn];        // x split hi (bf16)
__device__ __nv_bfloat16 g_xl[Mn * Dn];        // x split lo
__device__ __nv_bfloat16 g_Wh[4 * Dn * Dn];    // W^T split hi (4 weights, [n][k])
__device__ __nv_bfloat16 g_Wl[4 * Dn * Dn];    // W^T split lo
__device__ float g_Q[Mn * Dn];                 // [b,h,s,dk] tf32-rounded, scaled
__device__ float g_K[Mn * Dn];                 // tf32-rounded
__device__ float g_V[Mn * Dn];                 // tf32-rounded
__device__ __nv_bfloat16 g_ah[Mn * Dn];        // attn out hi [b,s,d]
__device__ __nv_bfloat16 g_al[Mn * Dn];        // attn out lo
__device__ float g_cos[Sn * 32];
__device__ float g_sin[Sn * 32];

// ---------------------------------------------------------------------------
// PTX helpers (base sm_103 target: cp.async / ldmatrix / mma.sync)
// ---------------------------------------------------------------------------
__device__ __forceinline__ uint32_t s2u(const void* p) {
    uint32_t a;
    asm("{ .reg .u64 t; cvta.to.shared.u64 t, %1; cvt.u32.u64 %0, t; }"
        : "=r"(a) : "l"(p));
    return a;
}

__device__ __forceinline__ void cpa16(uint32_t dst, const void* src) {
    asm volatile("cp.async.cg.shared.global [%0], [%1], 16;"
                 :: "r"(dst), "l"(src) : "memory");
}
#define CP_COMMIT() asm volatile("cp.async.commit_group;" ::: "memory")
#define CP_WAIT1() asm volatile("cp.async.wait_group 1;" ::: "memory")
#define CP_WAIT0() asm volatile("cp.async.wait_group 0;" ::: "memory")

__device__ __forceinline__ void ldsm4(uint32_t addr, uint32_t* r) {
    asm volatile(
        "ldmatrix.sync.aligned.m8n8.x4.shared.b16 {%0,%1,%2,%3}, [%4];"
        : "=r"(r[0]), "=r"(r[1]), "=r"(r[2]), "=r"(r[3]) : "r"(addr));
}

__device__ __forceinline__ void mma_bf16(float* c, const uint32_t* a,
                                         uint32_t b0, uint32_t b1) {
    asm volatile(
        "mma.sync.aligned.m16n8k16.row.col.f32.bf16.bf16.f32 "
        "{%0,%1,%2,%3}, {%4,%5,%6,%7}, {%8,%9}, {%0,%1,%2,%3};"
        : "+f"(c[0]), "+f"(c[1]), "+f"(c[2]), "+f"(c[3])
        : "r"(a[0]), "r"(a[1]), "r"(a[2]), "r"(a[3]), "r"(b0), "r"(b1));
}

__device__ __forceinline__ void mma_tf32(float* c, const float* a, float b0,
                                         float b1) {
    asm volatile(
        "mma.sync.aligned.m16n8k8.row.col.f32.tf32.tf32.f32 "
        "{%0,%1,%2,%3}, {%4,%5,%6,%7}, {%8,%9}, {%0,%1,%2,%3};"
        : "+f"(c[0]), "+f"(c[1]), "+f"(c[2]), "+f"(c[3])
        : "r"(__float_as_uint(a[0])), "r"(__float_as_uint(a[1])),
          "r"(__float_as_uint(a[2])), "r"(__float_as_uint(a[3])),
          "r"(__float_as_uint(b0)), "r"(__float_as_uint(b1)));
}

__device__ __forceinline__ float tf32r(float x) {
    uint32_t r;
    asm("cvt.rna.tf32.f32 %0, %1;" : "=r"(r) : "f"(x));
    return __uint_as_float(r);
}

// Fast exp2 on the FMA pipe (input clamped to [-126, 0]); ~4e-5 rel err.
__device__ __forceinline__ float exp2_fast(float y) {
    y = fmaxf(y, -126.0f);
    float fe = y + 12582912.0f;                 // round-to-int via magic
    int ei = __float_as_int(fe) << 23;          // integer part -> exponent bits
    float fr = y - (fe - 12582912.0f);          // frac in [-0.5, 0.5]
    float p = 0.0096181291f;
    p = fmaf(p, fr, 0.0555041087f);
    p = fmaf(p, fr, 0.2402264923f);
    p = fmaf(p, fr, 0.6931471806f);
    p = fmaf(p, fr, 1.0f);
    return __int_as_float(__float_as_int(p) + ei);
}

// ---------------------------------------------------------------------------
// Prep kernels
// ---------------------------------------------------------------------------
__global__ void rope_tab_kernel(const int* __restrict__ pos) {
    int idx = blockIdx.x * 256 + threadIdx.x;
    if (idx >= Sn * 32) return;
    int s = idx >> 5;
    int f = idx & 31;
    float inv = expf(-(float)f * (logf(10000.0f) / 32.0f));
    float a = (float)pos[s] * inv;
    g_cos[idx] = cosf(a);
    g_sin[idx] = sinf(a);
}

__global__ void split_x_kernel(const float* __restrict__ x,
                               __nv_bfloat16* __restrict__ xh,
                               __nv_bfloat16* __restrict__ xl) {
    size_t i = ((size_t)blockIdx.x * 256 + threadIdx.x) * 4;
    float4 a = *(const float4*)(x + i);
    float v[4] = {a.x, a.y, a.z, a.w};
    __nv_bfloat162 h2[2], l2[2];
#pragma unroll
    for (int p = 0; p < 2; ++p) {
        __nv_bfloat16 h0 = __float2bfloat16(v[2 * p]);
        __nv_bfloat16 h1 = __float2bfloat16(v[2 * p + 1]);
        h2[p] = __nv_bfloat162(h0, h1);
        l2[p] = __nv_bfloat162(
            __float2bfloat16(v[2 * p] - __bfloat162float(h0)),
            __float2bfloat16(v[2 * p + 1] - __bfloat162float(h1)));
    }
    *(uint2*)(xh + i) = *(uint2*)h2;
    *(uint2*)(xl + i) = *(uint2*)l2;
}

// W[k][n] -> WT[n][k] bf16 split
__global__ void transpose_split_kernel(const float* __restrict__ W,
                                       __nv_bfloat16* __restrict__ Th,
                                       __nv_bfloat16* __restrict__ Tl) {
    __shared__ float t[32][33];
    int n0 = blockIdx.x * 32, k0 = blockIdx.y * 32;
    int tx = threadIdx.x;
#pragma unroll
    for (int i = threadIdx.y; i < 32; i += 8)
        t[i][tx] = W[(size_t)(k0 + i) * Dn + n0 + tx];
    __syncthreads();
#pragma unroll
    for (int i = threadIdx.y; i < 32; i += 8) {
        float a = t[tx][i];
        __nv_bfloat16 hi = __float2bfloat16(a);
        float lo = a - __bfloat162float(hi);
        Th[(size_t)(n0 + i) * Dn + k0 + tx] = hi;
        Tl[(size_t)(n0 + i) * Dn + k0 + tx] = __float2bfloat16(lo);
    }
}

// ---------------------------------------------------------------------------
// Tensor-core GEMM (mma.sync bf16, 3-pass split):
//   out[8192, 1024] = A @ B   with B supplied as [n][k] (W^T)
// MODE 0: Q (RoPE + QSCALE + tf32 round, head-major)
// MODE 3: K (RoPE + tf32 round, head-major)
// MODE 1: V (tf32 round, head-major)
// MODE 2: final output (plain row-major)
// ---------------------------------------------------------------------------
constexpr int TM = 128, TN = 128, TK = 32;
constexpr int NCHUNK = Dn / TK;       // 32
constexpr int ROWB = 80;              // padded row stride (bytes) for 32 bf16
constexpr int PLANE = 128 * ROWB;     // 10240 bytes per plane
constexpr int STAGE = 4 * PLANE;      // A_hi, A_lo, B_hi, B_lo = 40960
constexpr int GEMM_SMEM = 2 * STAGE;  // 81920

__device__ __forceinline__ void load_stage(
    uint32_t stb, const __nv_bfloat16* __restrict__ Ah,
    const __nv_bfloat16* __restrict__ Al, const __nv_bfloat16* __restrict__ Bh,
    const __nv_bfloat16* __restrict__ Bl, int m0, int n0, int k0, int tid) {
#pragma unroll
    for (int i = 0; i < 8; ++i) {
        int op = tid + i * 256;
        int plane = op >> 9;
        int w = op & 511;
        int r = w >> 2, ch = w & 3;
        uint32_t dst = stb + plane * PLANE + r * ROWB + ch * 16;
        const __nv_bfloat16* src;
        if (plane == 0)      src = Ah + (size_t)(m0 + r) * Dn + k0 + ch * 8;
        else if (plane == 1) src = Al + (size_t)(m0 + r) * Dn + k0 + ch * 8;
        else if (plane == 2) src = Bh + (size_t)(n0 + r) * Dn + k0 + ch * 8;
        else                 src = Bl + (size_t)(n0 + r) * Dn + k0 + ch * 8;
        cpa16(dst, src);
    }
}

template <int MODE>
__global__ __launch_bounds__(256) void gemm_mma_kernel(
    const __nv_bfloat16* __restrict__ Ah, const __nv_bfloat16* __restrict__ Al,
    const __nv_bfloat16* __restrict__ Bh, const __nv_bfloat16* __restrict__ Bl,
    float* __restrict__ out) {
    extern __shared__ char smem[];
    const uint32_t sb = s2u(smem);
    const int tid = threadIdx.x;
    const int wid = tid >> 5, lane = tid & 31;
    const int warp_m = wid & 3, warp_n = wid >> 2;
    const int m0 = blockIdx.y * TM, n0 = blockIdx.x * TN;

    float acc[2][8][4];
#pragma unroll
    for (int mf = 0; mf < 2; ++mf)
#pragma unroll
        for (int nf = 0; nf < 8; ++nf)
#pragma unroll
            for (int j = 0; j < 4; ++j) acc[mf][nf][j] = 0.0f;

    const int lrow = lane & 15;
    const int lcol = (lane >> 4) * 16;
    const uint32_t aOff = (uint32_t)((warp_m * 32 + lrow) * ROWB + lcol);
    const uint32_t bOff = (uint32_t)(2 * PLANE + (warp_n * 64 + lrow) * ROWB + lcol);

    load_stage(sb, Ah, Al, Bh, Bl, m0, n0, 0, tid);
    CP_COMMIT();

    for (int c = 0; c < NCHUNK; ++c) {
        if (c + 1 < NCHUNK) {
            load_stage(sb + ((c + 1) & 1) * STAGE, Ah, Al, Bh, Bl, m0, n0,
                       (c + 1) * TK, tid);
            CP_COMMIT();
            CP_WAIT1();
        } else {
            CP_WAIT0();
        }
        __syncthreads();

        const uint32_t stb = sb + (c & 1) * STAGE;
#pragma unroll
        for (int ks = 0; ks < 2; ++ks) {
            const uint32_t kb = ks * 32;
            uint32_t ah[2][4], al[2][4];
            ldsm4(stb + aOff + kb, ah[0]);
            ldsm4(stb + aOff + 16 * ROWB + kb, ah[1]);
            ldsm4(stb + PLANE + aOff + kb, al[0]);
            ldsm4(stb + PLANE + aOff + 16 * ROWB + kb, al[1]);
            uint32_t bh[4][4], bl[4][4];
#pragma unroll
            for (int p = 0; p < 4; ++p) {
                ldsm4(stb + bOff + p * 16 * ROWB + kb, bh[p]);
                ldsm4(stb + PLANE + bOff + p * 16 * ROWB + kb, bl[p]);
            }
#pragma unroll
            for (int mf = 0; mf < 2; ++mf)
#pragma unroll
                for (int nf = 0; nf < 8; ++nf) {
                    const int pr = nf >> 1, wh = nf & 1;
                    mma_bf16(acc[mf][nf], ah[mf], bh[pr][wh], bh[pr][2 + wh]);
                    mma_bf16(acc[mf][nf], ah[mf], bl[pr][wh], bl[pr][2 + wh]);
                    mma_bf16(acc[mf][nf], al[mf], bh[pr][wh], bh[pr][2 + wh]);
                }
        }
        __syncthreads();
    }

    // Epilogue
    const int gid = lane >> 2, tig = lane & 3;
#pragma unroll
    for (int mf = 0; mf < 2; ++mf)
#pragma unroll
        for (int nf = 0; nf < 8; ++nf) {
            const float* cc = acc[mf][nf];
            const int row0 = m0 + warp_m * 32 + mf * 16 + gid;
            const int dcol = nf * 8 + tig * 2;
            if (MODE == 2) {
                const int col = n0 + warp_n * 64 + dcol;
                *(float2*)(out + (size_t)row0 * Dn + col) =
                    make_float2(cc[0], cc[1]);
                *(float2*)(out + (size_t)(row0 + 8) * Dn + col) =
                    make_float2(cc[2], cc[3]);
            } else {
                const int h = (n0 + warp_n * 64) >> 6;
#pragma unroll
                for (int rr = 0; rr < 2; ++rr) {
                    const int row = row0 + rr * 8;
                    const int b_ = row >> 11, s_ = row & (Sn - 1);
                    float e0 = cc[rr * 2], e1 = cc[rr * 2 + 1];
                    if (MODE == 0 || MODE == 3) {
                        const int f = nf * 4 + tig;
                        const float cz = g_cos[s_ * 32 + f];
                        const float sz = g_sin[s_ * 32 + f];
                        const float r1 = e0 * cz - e1 * sz;
                        const float r2 = e0 * sz + e1 * cz;
                        e0 = r1; e1 = r2;
                    }
                    if (MODE == 0) { e0 *= QSCALE; e1 *= QSCALE; }
                    e0 = tf32r(e0); e1 = tf32r(e1);
                    *(float2*)(out + (((size_t)b_ * Hn + h) * Sn + s_) * DKn +
                               dcol) = make_float2(e0, e1);
                }
            }
        }
}

// ---------------------------------------------------------------------------
// Flash attention on tensor cores (tf32 mma + FFMA-pipe exp2).
// CTA = 128 queries of one (b,h); 8 warps, each owns 16 query rows.
// K/V tiles of 64 keys, double-buffered via cp.async, padded stride 68 floats.
// ---------------------------------------------------------------------------
constexpr int KV_STRIDE = 68;                 // floats
constexpr int TILE_F = 64 * KV_STRIDE;        // 4352 floats per tile
constexpr int STAGE_B = 2 * TILE_F * 4;       // K+V stage bytes = 34816
constexpr int PS_OFF_F = 4 * TILE_F;          // 17408 floats
constexpr int ATTN_SMEM = (PS_OFF_F + 8 * 16 * KV_STRIDE) * 4;  // 104448 B

__device__ __forceinline__ void load_kv(uint32_t dstb, const float* __restrict__ Kb,
                                        const float* __restrict__ Vb, int kt,
                                        int tid) {
    const float* s0 = Kb + (size_t)kt * 64 * 64;
    const float* s1 = Vb + (size_t)kt * 64 * 64;
#pragma unroll
    for (int i = 0; i < 8; ++i) {
        int idx = tid + i * 256;
        int t = idx >> 10;
        int w = idx & 1023;
        int r = w >> 4, ch = w & 15;
        uint32_t d = dstb + (uint32_t)(t * (TILE_F * 4) + r * (KV_STRIDE * 4) +
                                       ch * 16);
        const float* s = (t ? s1 : s0) + r * 64 + ch * 4;
        cpa16(d, s);
    }
}

__global__ __launch_bounds__(256, 1) void attn_tc_kernel(
    const float* __restrict__ Q, const float* __restrict__ K,
    const float* __restrict__ V, __nv_bfloat16* __restrict__ Oh,
    __nv_bfloat16* __restrict__ Ol) {
    extern __shared__ float sm[];
    const uint32_t smb = s2u(sm);
    const int tid = threadIdx.x;
    const int wid = tid >> 5, lane = tid & 31;
    const int gid = lane >> 2, tig = lane & 3;
    const int bh = blockIdx.y;
    const int qt = (int)gridDim.x - 1 - (int)blockIdx.x;  // big tiles first
    const int q0 = qt * 128;

    const float* Qb = Q + ((size_t)bh * Sn + q0) * DKn;
    const float* Kb = K + (size_t)bh * Sn * DKn;
    const float* Vb = V + (size_t)bh * Sn * DKn;

    // Q fragments (already tf32-rounded & scaled by QSCALE in producer)
    const int lr = wid * 16 + gid;  // local query row for c0/c1
    float aq[8][4];
#pragma unroll
    for (int kf = 0; kf < 8; ++kf) {
        const float* p = Qb + (size_t)lr * DKn + kf * 8 + tig;
        aq[kf][0] = p[0];
        aq[kf][1] = p[8 * DKn];
        aq[kf][2] = p[4];
        aq[kf][3] = p[8 * DKn + 4];
    }

    float oacc[8][4];
#pragma unroll
    for (int nf = 0; nf < 8; ++nf)
#pragma unroll
        for (int j = 0; j < 4; ++j) oacc[nf][j] = 0.0f;
    float mr0 = -1e30f, mr1 = -1e30f, sl0 = 0.0f, sl1 = 0.0f;

    const int nkt = 2 * qt + 2;
    load_kv(smb, Kb, Vb, 0, tid);
    CP_COMMIT();

    for (int kt = 0; kt < nkt; ++kt) {
        if (kt + 1 < nkt) {
            load_kv(smb + ((kt + 1) & 1) * STAGE_B, Kb, Vb, kt + 1, tid);
            CP_COMMIT();
            CP_WAIT1();
        } else {
            CP_WAIT0();
        }
        __syncthreads();
        const float* Ks = sm + ((kt & 1) ? 2 * TILE_F : 0);
        const float* Vx = Ks + TILE_F;

        // S = Q . K^T  (scores in log2 units)
        float sacc[8][4];
#pragma unroll
        for (int nf = 0; nf < 8; ++nf)
#pragma unroll
            for (int j = 0; j < 4; ++j) sacc[nf][j] = 0.0f;
#pragma unroll
        for (int kf = 0; kf < 8; ++kf) {
#pragma unroll
            for (int nf = 0; nf < 8; ++nf) {
                const float* bp = Ks + (nf * 8 + gid) * KV_STRIDE + kf * 8 + tig;
                mma_tf32(sacc[nf], aq[kf], bp[0], bp[4]);
            }
        }

        // causal mask on diagonal tiles
        if (kt >= 2 * qt) {
            const int cb = kt * 64 + tig * 2;
            const int r0g = q0 + lr;
#pragma unroll
            for (int nf = 0; nf < 8; ++nf) {
                const int c0 = cb + nf * 8;
                if (c0 > r0g) sacc[nf][0] = -1e30f;
                if (c0 + 1 > r0g) sacc[nf][1] = -1e30f;
                if (c0 > r0g + 8) sacc[nf][2] = -1e30f;
                if (c0 + 1 > r0g + 8) sacc[nf][3] = -1e30f;
            }
        }

        // online softmax (rows owned per-warp; reduce over 4 lanes)
        float t0 = -1e30f, t1 = -1e30f;
#pragma unroll
        for (int nf = 0; nf < 8; ++nf) {
            t0 = fmaxf(t0, fmaxf(sacc[nf][0], sacc[nf][1]));
            t1 = fmaxf(t1, fmaxf(sacc[nf][2], sacc[nf][3]));
        }
        t0 = fmaxf(t0, __shfl_xor_sync(0xffffffffu, t0, 1));
        t0 = fmaxf(t0, __shfl_xor_sync(0xffffffffu, t0, 2));
        t1 = fmaxf(t1, __shfl_xor_sync(0xffffffffu, t1, 1));
        t1 = fmaxf(t1, __shfl_xor_sync(0xffffffffu, t1, 2));
        const float nm0 = fmaxf(mr0, t0), nm1 = fmaxf(mr1, t1);
        const float cr0 = exp2_fast(mr0 - nm0), cr1 = exp2_fast(mr1 - nm1);
        mr0 = nm0; mr1 = nm1;
        float s0 = 0.0f, s1 = 0.0f;
#pragma unroll
        for (int nf = 0; nf < 8; ++nf) {
            sacc[nf][0] = exp2_fast(sacc[nf][0] - nm0);
            sacc[nf][1] = exp2_fast(sacc[nf][1] - nm0);
            sacc[nf][2] = exp2_fast(sacc[nf][2] - nm1);
            sacc[nf][3] = exp2_fast(sacc[nf][3] - nm1);
            s0 += sacc[nf][0] + sacc[nf][1];
            s1 += sacc[nf][2] + sacc[nf][3];
        }
        s0 += __shfl_xor_sync(0xffffffffu, s0, 1);
        s0 += __shfl_xor_sync(0xffffffffu, s0, 2);
        s1 += __shfl_xor_sync(0xffffffffu, s1, 1);
        s1 += __shfl_xor_sync(0xffffffffu, s1, 2);
        sl0 = sl0 * cr0 + s0;
        sl1 = sl1 * cr1 + s1;
#pragma unroll
        for (int nf = 0; nf < 8; ++nf) {
            oacc[nf][0] *= cr0;
            oacc[nf][1] *= cr0;
            oacc[nf][2] *= cr1;
            oacc[nf][3] *= cr1;
        }

        // store P (tf32-rounded) to per-warp smem, relayout accum -> A-frag
        float* Pw = sm + PS_OFF_F + wid * (16 * KV_STRIDE);
#pragma unroll
        for (int nf = 0; nf < 8; ++nf) {
            const int cc = nf * 8 + tig * 2;
            Pw[gid * KV_STRIDE + cc] = tf32r(sacc[nf][0]);
            Pw[gid * KV_STRIDE + cc + 1] = tf32r(sacc[nf][1]);
            Pw[(gid + 8) * KV_STRIDE + cc] = tf32r(sacc[nf][2]);
            Pw[(gid + 8) * KV_STRIDE + cc + 1] = tf32r(sacc[nf][3]);
        }
        __syncwarp();

        // O += P . V
#pragma unroll
        for (int kf = 0; kf < 8; ++kf) {
            float a[4];
            a[0] = Pw[gid * KV_STRIDE + kf * 8 + tig];
            a[1] = Pw[(gid + 8) * KV_STRIDE + kf * 8 + tig];
            a[2] = Pw[gid * KV_STRIDE + kf * 8 + tig + 4];
            a[3] = Pw[(gid + 8) * KV_STRIDE + kf * 8 + tig + 4];
#pragma unroll
            for (int nf = 0; nf < 8; ++nf) {
                const float* vp = Vx + (kf * 8 + tig) * KV_STRIDE + nf * 8 + gid;
                mma_tf32(oacc[nf], a, vp[0], vp[4 * KV_STRIDE]);
            }
        }
        __syncwarp();
        __syncthreads();
    }

    // epilogue: normalize + bf16 hi/lo split store
    const float il0 = 1.0f / sl0, il1 = 1.0f / sl1;
    const int row0 = q0 + lr;
    const int b_ = bh >> 4, h = bh & 15;
    const size_t o0 = ((size_t)b_ * Sn + row0) * Dn + h * DKn;
    const size_t o1 = o0 + (size_t)8 * Dn;
#pragma unroll
    for (int nf = 0; nf < 8; ++nf) {
        const int col = nf * 8 + tig * 2;
        float v0 = oacc[nf][0] * il0, v1 = oacc[nf][1] * il0;
        float v2 = oacc[nf][2] * il1, v3 = oacc[nf][3] * il1;
        __nv_bfloat16 h0 = __float2bfloat16(v0), h1 = __float2bfloat16(v1);
        __nv_bfloat16 h2 = __float2bfloat16(v2), h3 = __float2bfloat16(v3);
        __nv_bfloat162 hv0(h0, h1), hv1(h2, h3);
        __nv_bfloat162 lv0(__float2bfloat16(v0 - __bfloat162float(h0)),
                           __float2bfloat16(v1 - __bfloat162float(h1)));
        __nv_bfloat162 lv1(__float2bfloat16(v2 - __bfloat162float(h2)),
                           __float2bfloat16(v3 - __bfloat162float(h3)));
        *(uint32_t*)(Oh + o0 + col) = *(uint32_t*)&hv0;
        *(uint32_t*)(Ol + o0 + col) = *(uint32_t*)&lv0;
        *(uint32_t*)(Oh + o1 + col) = *(uint32_t*)&hv1;
        *(uint32_t*)(Ol + o1 + col) = *(uint32_t*)&lv1;
    }
}

// ---------------------------------------------------------------------------
extern "C" void kernel_launch(void* const* d_in, const int* in_sizes, int n_in,
                              void* d_out, int out_size) {
    const float* x  = (const float*)d_in[0];
    const float* Wq = (const float*)d_in[1];
    const float* Wk = (const float*)d_in[2];
    const float* Wv = (const float*)d_in[3];
    const float* Wo = (const float*)d_in[4];
    const int* pos  = (const int*)d_in[5];
    float* out = (float*)d_out;

    __nv_bfloat16 *pxh, *pxl, *pWh, *pWl, *pah, *pal;
    float *pQ, *pK, *pV;
    cudaGetSymbolAddress((void**)&pxh, g_xh);
    cudaGetSymbolAddress((void**)&pxl, g_xl);
    cudaGetSymbolAddress((void**)&pWh, g_Wh);
    cudaGetSymbolAddress((void**)&pWl, g_Wl);
    cudaGetSymbolAddress((void**)&pQ, g_Q);
    cudaGetSymbolAddress((void**)&pK, g_K);
    cudaGetSymbolAddress((void**)&pV, g_V);
    cudaGetSymbolAddress((void**)&pah, g_ah);
    cudaGetSymbolAddress((void**)&pal, g_al);

    cudaFuncSetAttribute((const void*)gemm_mma_kernel<0>,
                         cudaFuncAttributeMaxDynamicSharedMemorySize, GEMM_SMEM);
    cudaFuncSetAttribute((const void*)gemm_mma_kernel<1>,
                         cudaFuncAttributeMaxDynamicSharedMemorySize, GEMM_SMEM);
    cudaFuncSetAttribute((const void*)gemm_mma_kernel<2>,
                         cudaFuncAttributeMaxDynamicSharedMemorySize, GEMM_SMEM);
    cudaFuncSetAttribute((const void*)gemm_mma_kernel<3>,
                         cudaFuncAttributeMaxDynamicSharedMemorySize, GEMM_SMEM);
    cudaFuncSetAttribute((const void*)attn_tc_kernel,
                         cudaFuncAttributeMaxDynamicSharedMemorySize, ATTN_SMEM);

    rope_tab_kernel<<<(Sn * 32 + 255) / 256, 256>>>(pos);
    split_x_kernel<<<Mn * Dn / 1024, 256>>>(x, pxh, pxl);
    const float* Ws[4] = {Wq, Wk, Wv, Wo};
    for (int w = 0; w < 4; ++w)
        transpose_split_kernel<<<dim3(32, 32), dim3(32, 8)>>>(
            Ws[w], pWh + (size_t)w * Dn * Dn, pWl + (size_t)w * Dn * Dn);

    dim3 gg(Dn / TN, Mn / TM);  // (8, 64)
    gemm_mma_kernel<0><<<gg, 256, GEMM_SMEM>>>(pxh, pxl, pWh, pWl, pQ);
    gemm_mma_kernel<3><<<gg, 256, GEMM_SMEM>>>(pxh, pxl, pWh + Dn * Dn,
                                               pWl + Dn * Dn, pK);
    gemm_mma_kernel<1><<<gg, 256, GEMM_SMEM>>>(pxh, pxl, pWh + 2 * Dn * Dn,
                                               pWl + 2 * Dn * Dn, pV);

    dim3 agrid(Sn / 128, Bn * Hn);  // (16, 64)
    attn_tc_kernel<<<agrid, 256, ATTN_SMEM>>>(pQ, pK, pV, pah, pal);

    gemm_mma_kernel<2><<<gg, 256, GEMM_SMEM>>>(pah, pal, pWh + 3 * Dn * Dn,
                                               pWl + 3 * Dn * Dn, out);
}

// round 6
// speedup vs baseline: 3.5986x; 1.5448x over previous
#include <cuda_runtime.h>
#include <cuda_fp16.h>
#include <math.h>
#include <cstdint>

// Problem constants
constexpr int Bn = 4;
constexpr int Sn = 2048;
constexpr int Dn = 1024;
constexpr int Hn = 16;
constexpr int DKn = 64;
constexpr int Mn = Bn * Sn;  // 8192

// Q pre-scale: 1/sqrt(64) * log2(e)
#define QSCALE 0.18033688011112042f

// ---------------------------------------------------------------------------
// Scratch (static device arrays — no allocation allowed)
// ---------------------------------------------------------------------------
__device__ __half g_xh[Mn * Dn];          // x split hi
__device__ __half g_xl[Mn * Dn];          // x split lo
__device__ __half g_Wh[4 * Dn * Dn];      // W^T fp16 (4 weights, [n][k])
__device__ __half g_Q[Mn * Dn];           // [b,h,s,dk] fp16, scaled+RoPE
__device__ __half g_K[Mn * Dn];           // fp16, RoPE
__device__ __half g_V[Mn * Dn];           // fp16
__device__ __half g_ah[Mn * Dn];          // attn out hi [b,s,d]
__device__ __half g_al[Mn * Dn];          // attn out lo
__device__ float g_cos[Sn * 32];
__device__ float g_sin[Sn * 32];

// ---------------------------------------------------------------------------
// PTX helpers
// ---------------------------------------------------------------------------
__device__ __forceinline__ uint32_t s2u(const void* p) {
    uint32_t a;
    asm("{ .reg .u64 t; cvta.to.shared.u64 t, %1; cvt.u32.u64 %0, t; }"
        : "=r"(a) : "l"(p));
    return a;
}

__device__ __forceinline__ void cpa16(uint32_t dst, const void* src) {
    asm volatile("cp.async.cg.shared.global [%0], [%1], 16;"
                 :: "r"(dst), "l"(src) : "memory");
}
#define CP_COMMIT() asm volatile("cp.async.commit_group;" ::: "memory")
#define CP_WAIT1() asm volatile("cp.async.wait_group 1;" ::: "memory")
#define CP_WAIT0() asm volatile("cp.async.wait_group 0;" ::: "memory")

__device__ __forceinline__ void ldsm4(uint32_t addr, uint32_t* r) {
    asm volatile(
        "ldmatrix.sync.aligned.m8n8.x4.shared.b16 {%0,%1,%2,%3}, [%4];"
        : "=r"(r[0]), "=r"(r[1]), "=r"(r[2]), "=r"(r[3]) : "r"(addr));
}

__device__ __forceinline__ void ldsm4t(uint32_t addr, uint32_t* r) {
    asm volatile(
        "ldmatrix.sync.aligned.m8n8.x4.trans.shared.b16 {%0,%1,%2,%3}, [%4];"
        : "=r"(r[0]), "=r"(r[1]), "=r"(r[2]), "=r"(r[3]) : "r"(addr));
}

__device__ __forceinline__ void mma_f16(float* c, const uint32_t* a,
                                        uint32_t b0, uint32_t b1) {
    asm volatile(
        "mma.sync.aligned.m16n8k16.row.col.f32.f16.f16.f32 "
        "{%0,%1,%2,%3}, {%4,%5,%6,%7}, {%8,%9}, {%0,%1,%2,%3};"
        : "+f"(c[0]), "+f"(c[1]), "+f"(c[2]), "+f"(c[3])
        : "r"(a[0]), "r"(a[1]), "r"(a[2]), "r"(a[3]), "r"(b0), "r"(b1));
}

// Fast exp2 on the FMA pipe (input <= 0); ~4e-5 rel err.
__device__ __forceinline__ float exp2_fast(float y) {
    y = fmaxf(y, -126.0f);
    float fe = y + 12582912.0f;
    int ei = __float_as_int(fe) << 23;
    float fr = y - (fe - 12582912.0f);
    float p = 0.0096181291f;
    p = fmaf(p, fr, 0.0555041087f);
    p = fmaf(p, fr, 0.2402264923f);
    p = fmaf(p, fr, 0.6931471806f);
    p = fmaf(p, fr, 1.0f);
    return __int_as_float(__float_as_int(p) + ei);
}

// ---------------------------------------------------------------------------
// Prep kernels
// ---------------------------------------------------------------------------
__global__ void rope_tab_kernel(const int* __restrict__ pos) {
    int idx = blockIdx.x * 256 + threadIdx.x;
    if (idx >= Sn * 32) return;
    int s = idx >> 5;
    int f = idx & 31;
    float inv = expf(-(float)f * (logf(10000.0f) / 32.0f));
    float a = (float)pos[s] * inv;
    g_cos[idx] = cosf(a);
    g_sin[idx] = sinf(a);
}

__global__ void split_x_kernel(const float* __restrict__ x,
                               __half* __restrict__ xh,
                               __half* __restrict__ xl) {
    size_t i = ((size_t)blockIdx.x * 256 + threadIdx.x) * 4;
    float4 a = *(const float4*)(x + i);
    float v[4] = {a.x, a.y, a.z, a.w};
    __half2 h2[2], l2[2];
#pragma unroll
    for (int p = 0; p < 2; ++p) {
        __half h0 = __float2half_rn(v[2 * p]);
        __half h1 = __float2half_rn(v[2 * p + 1]);
        h2[p] = __half2(h0, h1);
        l2[p] = __half2(__float2half_rn(v[2 * p] - __half2float(h0)),
                        __float2half_rn(v[2 * p + 1] - __half2float(h1)));
    }
    *(uint2*)(xh + i) = *(uint2*)h2;
    *(uint2*)(xl + i) = *(uint2*)l2;
}

// W[k][n] -> WT[n][k] fp16
__global__ void transpose_half_kernel(const float* __restrict__ W,
                                      __half* __restrict__ Th) {
    __shared__ float t[32][33];
    int n0 = blockIdx.x * 32, k0 = blockIdx.y * 32;
    int tx = threadIdx.x;
#pragma unroll
    for (int i = threadIdx.y; i < 32; i += 8)
        t[i][tx] = W[(size_t)(k0 + i) * Dn + n0 + tx];
    __syncthreads();
#pragma unroll
    for (int i = threadIdx.y; i < 32; i += 8)
        Th[(size_t)(n0 + i) * Dn + k0 + tx] = __float2half_rn(t[tx][i]);
}

// ---------------------------------------------------------------------------
// Tensor-core GEMM (mma.sync fp16, 2-pass split on A only):
//   out[8192, 1024] = (Ah + Al) @ B,  B = W^T fp16 [n][k]
// CTA 128x128, K-chunk 32, 2-stage cp.async pipeline, 3 smem planes.
// MODE 0: Q (RoPE + QSCALE, fp16 head-major)
// MODE 3: K (RoPE, fp16 head-major)
// MODE 1: V (fp16 head-major)
// MODE 2: final output (fp32 row-major)
// ---------------------------------------------------------------------------
constexpr int TM = 128, TN = 128, TK = 32;
constexpr int NCHUNK = Dn / TK;       // 32
constexpr int ROWB = 80;              // bytes per 32-half row (64B data + pad)
constexpr int PLANE = 128 * ROWB;     // 10240
constexpr int STAGE = 3 * PLANE;      // A_hi, A_lo, B = 30720
constexpr int GEMM_SMEM = 2 * STAGE;  // 61440

__device__ __forceinline__ void load_stage(uint32_t stb,
                                           const __half* __restrict__ Ah,
                                           const __half* __restrict__ Al,
                                           const __half* __restrict__ Bh,
                                           int m0, int n0, int k0, int tid) {
#pragma unroll
    for (int i = 0; i < 6; ++i) {
        int op = tid + i * 256;
        int plane = op >> 9;
        int w = op & 511;
        int r = w >> 2, ch = w & 3;
        uint32_t dst = stb + plane * PLANE + r * ROWB + ch * 16;
        const __half* src;
        if (plane == 0)      src = Ah + (size_t)(m0 + r) * Dn + k0 + ch * 8;
        else if (plane == 1) src = Al + (size_t)(m0 + r) * Dn + k0 + ch * 8;
        else                 src = Bh + (size_t)(n0 + r) * Dn + k0 + ch * 8;
        cpa16(dst, src);
    }
}

template <int MODE>
__global__ __launch_bounds__(256) void gemm_mma_kernel(
    const __half* __restrict__ Ah, const __half* __restrict__ Al,
    const __half* __restrict__ Bh, void* __restrict__ outv) {
    extern __shared__ char smem[];
    const uint32_t sb = s2u(smem);
    const int tid = threadIdx.x;
    const int wid = tid >> 5, lane = tid & 31;
    const int warp_m = wid & 3, warp_n = wid >> 2;
    const int m0 = blockIdx.y * TM, n0 = blockIdx.x * TN;

    float acc[2][8][4];
#pragma unroll
    for (int mf = 0; mf < 2; ++mf)
#pragma unroll
        for (int nf = 0; nf < 8; ++nf)
#pragma unroll
            for (int j = 0; j < 4; ++j) acc[mf][nf][j] = 0.0f;

    const int lrow = lane & 15;
    const int lcol = (lane >> 4) * 16;
    const uint32_t aOff = (uint32_t)((warp_m * 32 + lrow) * ROWB + lcol);
    const uint32_t bOff = (uint32_t)(2 * PLANE + (warp_n * 64 + lrow) * ROWB + lcol);

    load_stage(sb, Ah, Al, Bh, m0, n0, 0, tid);
    CP_COMMIT();

    for (int c = 0; c < NCHUNK; ++c) {
        if (c + 1 < NCHUNK) {
            load_stage(sb + ((c + 1) & 1) * STAGE, Ah, Al, Bh, m0, n0,
                       (c + 1) * TK, tid);
            CP_COMMIT();
            CP_WAIT1();
        } else {
            CP_WAIT0();
        }
        __syncthreads();

        const uint32_t stb = sb + (c & 1) * STAGE;
#pragma unroll
        for (int ks = 0; ks < 2; ++ks) {
            const uint32_t kb = ks * 32;
            uint32_t ah[2][4], al[2][4];
            ldsm4(stb + aOff + kb, ah[0]);
            ldsm4(stb + aOff + 16 * ROWB + kb, ah[1]);
            ldsm4(stb + PLANE + aOff + kb, al[0]);
            ldsm4(stb + PLANE + aOff + 16 * ROWB + kb, al[1]);
            uint32_t bf[4][4];
#pragma unroll
            for (int p = 0; p < 4; ++p) ldsm4(stb + bOff + p * 16 * ROWB + kb, bf[p]);
#pragma unroll
            for (int mf = 0; mf < 2; ++mf)
#pragma unroll
                for (int nf = 0; nf < 8; ++nf) {
                    const int pr = nf >> 1, wh = nf & 1;
                    mma_f16(acc[mf][nf], ah[mf], bf[pr][wh], bf[pr][2 + wh]);
                    mma_f16(acc[mf][nf], al[mf], bf[pr][wh], bf[pr][2 + wh]);
                }
        }
        __syncthreads();
    }

    // Epilogue
    const int gid = lane >> 2, tig = lane & 3;
#pragma unroll
    for (int mf = 0; mf < 2; ++mf)
#pragma unroll
        for (int nf = 0; nf < 8; ++nf) {
            const float* cc = acc[mf][nf];
            const int row0 = m0 + warp_m * 32 + mf * 16 + gid;
            const int dcol = nf * 8 + tig * 2;
            if (MODE == 2) {
                float* out = (float*)outv;
                const int col = n0 + warp_n * 64 + dcol;
                *(float2*)(out + (size_t)row0 * Dn + col) =
                    make_float2(cc[0], cc[1]);
                *(float2*)(out + (size_t)(row0 + 8) * Dn + col) =
                    make_float2(cc[2], cc[3]);
            } else {
                __half* out = (__half*)outv;
                const int h = (n0 + warp_n * 64) >> 6;
#pragma unroll
                for (int rr = 0; rr < 2; ++rr) {
                    const int row = row0 + rr * 8;
                    const int b_ = row >> 11, s_ = row & (Sn - 1);
                    float e0 = cc[rr * 2], e1 = cc[rr * 2 + 1];
                    if (MODE == 0 || MODE == 3) {
                        const int f = nf * 4 + tig;
                        const float cz = g_cos[s_ * 32 + f];
                        const float sz = g_sin[s_ * 32 + f];
                        const float r1 = e0 * cz - e1 * sz;
                        const float r2 = e0 * sz + e1 * cz;
                        e0 = r1; e1 = r2;
                    }
                    if (MODE == 0) { e0 *= QSCALE; e1 *= QSCALE; }
                    __half2 hv(__float2half_rn(e0), __float2half_rn(e1));
                    *(uint32_t*)(out + (((size_t)b_ * Hn + h) * Sn + s_) * DKn +
                                 dcol) = *(uint32_t*)&hv;
                }
            }
        }
}

// ---------------------------------------------------------------------------
// Flash attention, fp16 mma + FFMA exp2.
// CTA = 128 queries of one (b,h); 8 warps, each owns 16 query rows (m16).
// K/V fp16 tiles of 64 keys, double-buffered cp.async; row stride 144B.
// ---------------------------------------------------------------------------
constexpr int KVSB = 144;                       // bytes per 64-half row
constexpr int KVPLANE = 64 * KVSB;              // 9216 B per K or V tile
constexpr int STAGE_B = 2 * KVPLANE;            // 18432
constexpr int P_OFF = 2 * STAGE_B;              // 36864
constexpr int ATTN_SMEM = P_OFF + 8 * 16 * KVSB;  // 55296 B

__device__ __forceinline__ void load_kv(uint32_t dstb,
                                        const __half* __restrict__ Kb,
                                        const __half* __restrict__ Vb, int kt,
                                        int tid) {
    const __half* s0 = Kb + (size_t)kt * 64 * 64;
    const __half* s1 = Vb + (size_t)kt * 64 * 64;
#pragma unroll
    for (int i = 0; i < 4; ++i) {
        int idx = tid + i * 256;
        int t = idx >> 9;
        int w = idx & 511;
        int r = w >> 3, ch = w & 7;
        uint32_t d = dstb + (uint32_t)(t * KVPLANE + r * KVSB + ch * 16);
        const __half* s = (t ? s1 : s0) + r * 64 + ch * 8;
        cpa16(d, s);
    }
}

__global__ __launch_bounds__(256, 2) void attn_tc_kernel(
    const __half* __restrict__ Q, const __half* __restrict__ K,
    const __half* __restrict__ V, __half* __restrict__ Oh,
    __half* __restrict__ Ol) {
    extern __shared__ char smc[];
    const uint32_t smb = s2u(smc);
    const int tid = threadIdx.x;
    const int wid = tid >> 5, lane = tid & 31;
    const int gid = lane >> 2, tig = lane & 3;
    const int bh = blockIdx.y;
    const int qt = (int)gridDim.x - 1 - (int)blockIdx.x;  // big tiles first
    const int q0 = qt * 128;

    const __half* Qb = Q + ((size_t)bh * Sn + q0) * DKn;
    const __half* Kb = K + (size_t)bh * Sn * DKn;
    const __half* Vb = V + (size_t)bh * Sn * DKn;

    // Q fragments (fp16, already scaled+RoPE'd)
    const int lr = wid * 16 + gid;
    uint32_t aq[4][4];
#pragma unroll
    for (int kf = 0; kf < 4; ++kf) {
        const __half* p = Qb + (size_t)lr * DKn + kf * 16 + tig * 2;
        aq[kf][0] = *(const uint32_t*)(p);
        aq[kf][1] = *(const uint32_t*)(p + 8 * DKn);
        aq[kf][2] = *(const uint32_t*)(p + 8);
        aq[kf][3] = *(const uint32_t*)(p + 8 * DKn + 8);
    }

    float oacc[8][4];
#pragma unroll
    for (int nf = 0; nf < 8; ++nf)
#pragma unroll
        for (int j = 0; j < 4; ++j) oacc[nf][j] = 0.0f;
    float mr0 = -1e30f, mr1 = -1e30f, sl0 = 0.0f, sl1 = 0.0f;

    const int nkt = 2 * qt + 2;
    load_kv(smb, Kb, Vb, 0, tid);
    CP_COMMIT();

    const int lrow = lane & 15;
    const uint32_t kOffBase = (uint32_t)(lrow * KVSB + (lane >> 4) * 16);
    const uint32_t pOff = (uint32_t)(P_OFF + wid * 16 * KVSB + lrow * KVSB +
                                     (lane >> 4) * 16);
    // V b-frag (x4 trans): lanes 0-15 -> key rows (lane&15), lanes 16-31 -> +8 dk cols
    const uint32_t vOffBase = (uint32_t)(lrow * KVSB + (lane >> 4) * 16);

    for (int kt = 0; kt < nkt; ++kt) {
        if (kt + 1 < nkt) {
            load_kv(smb + ((kt + 1) & 1) * STAGE_B, Kb, Vb, kt + 1, tid);
            CP_COMMIT();
            CP_WAIT1();
        } else {
            CP_WAIT0();
        }
        __syncthreads();
        const uint32_t Ks = smb + (kt & 1) * STAGE_B;
        const uint32_t Vs = Ks + KVPLANE;

        // S = Q . K^T
        float sacc[8][4];
#pragma unroll
        for (int nf = 0; nf < 8; ++nf)
#pragma unroll
            for (int j = 0; j < 4; ++j) sacc[nf][j] = 0.0f;
#pragma unroll
        for (int kf = 0; kf < 4; ++kf) {
            uint32_t bk[4][4];
#pragma unroll
            for (int p = 0; p < 4; ++p)
                ldsm4(Ks + kOffBase + p * 16 * KVSB + kf * 32, bk[p]);
#pragma unroll
            for (int p = 0; p < 4; ++p) {
                mma_f16(sacc[2 * p], aq[kf], bk[p][0], bk[p][2]);
                mma_f16(sacc[2 * p + 1], aq[kf], bk[p][1], bk[p][3]);
            }
        }

        // causal mask on diagonal tiles
        if (kt >= 2 * qt) {
            const int cb = kt * 64 + tig * 2;
            const int r0g = q0 + lr;
#pragma unroll
            for (int nf = 0; nf < 8; ++nf) {
                const int c0 = cb + nf * 8;
                if (c0 > r0g) sacc[nf][0] = -1e30f;
                if (c0 + 1 > r0g) sacc[nf][1] = -1e30f;
                if (c0 > r0g + 8) sacc[nf][2] = -1e30f;
                if (c0 + 1 > r0g + 8) sacc[nf][3] = -1e30f;
            }
        }

        // online softmax (log2 domain)
        float t0 = -1e30f, t1 = -1e30f;
#pragma unroll
        for (int nf = 0; nf < 8; ++nf) {
            t0 = fmaxf(t0, fmaxf(sacc[nf][0], sacc[nf][1]));
            t1 = fmaxf(t1, fmaxf(sacc[nf][2], sacc[nf][3]));
        }
        t0 = fmaxf(t0, __shfl_xor_sync(0xffffffffu, t0, 1));
        t0 = fmaxf(t0, __shfl_xor_sync(0xffffffffu, t0, 2));
        t1 = fmaxf(t1, __shfl_xor_sync(0xffffffffu, t1, 1));
        t1 = fmaxf(t1, __shfl_xor_sync(0xffffffffu, t1, 2));
        const float nm0 = fmaxf(mr0, t0), nm1 = fmaxf(mr1, t1);
        const float cr0 = exp2_fast(mr0 - nm0), cr1 = exp2_fast(mr1 - nm1);
        mr0 = nm0; mr1 = nm1;
        float s0 = 0.0f, s1 = 0.0f;
#pragma unroll
        for (int nf = 0; nf < 8; ++nf) {
            sacc[nf][0] = exp2_fast(sacc[nf][0] - nm0);
            sacc[nf][1] = exp2_fast(sacc[nf][1] - nm0);
            sacc[nf][2] = exp2_fast(sacc[nf][2] - nm1);
            sacc[nf][3] = exp2_fast(sacc[nf][3] - nm1);
            s0 += sacc[nf][0] + sacc[nf][1];
            s1 += sacc[nf][2] + sacc[nf][3];
        }
        s0 += __shfl_xor_sync(0xffffffffu, s0, 1);
        s0 += __shfl_xor_sync(0xffffffffu, s0, 2);
        s1 += __shfl_xor_sync(0xffffffffu, s1, 1);
        s1 += __shfl_xor_sync(0xffffffffu, s1, 2);
        sl0 = sl0 * cr0 + s0;
        sl1 = sl1 * cr1 + s1;
#pragma unroll
        for (int nf = 0; nf < 8; ++nf) {
            oacc[nf][0] *= cr0;
            oacc[nf][1] *= cr0;
            oacc[nf][2] *= cr1;
            oacc[nf][3] *= cr1;
        }

        // write P (fp16) to per-warp smem region
        {
            char* Pw = smc + (P_OFF + wid * 16 * KVSB);
#pragma unroll
            for (int nf = 0; nf < 8; ++nf) {
                const int cc = nf * 8 + tig * 2;
                __half2 p0(__float2half_rn(sacc[nf][0]),
                           __float2half_rn(sacc[nf][1]));
                __half2 p1(__float2half_rn(sacc[nf][2]),
                           __float2half_rn(sacc[nf][3]));
                *(uint32_t*)(Pw + gid * KVSB + cc * 2) = *(uint32_t*)&p0;
                *(uint32_t*)(Pw + (gid + 8) * KVSB + cc * 2) = *(uint32_t*)&p1;
            }
        }
        __syncwarp();

        // O += P . V   (A = P via ldsm, B = V via ldsm.trans)
#pragma unroll
        for (int kf = 0; kf < 4; ++kf) {
            uint32_t ap[4];
            ldsm4(smb + pOff + kf * 32, ap);
#pragma unroll
            for (int p = 0; p < 4; ++p) {
                uint32_t bv[4];
                // key rows kf*16 + (lane&15), dk cols p*16 + (lane>>4)*8
                ldsm4t(Vs + (uint32_t)(kf * 16 * KVSB) + vOffBase +
                           (uint32_t)(p * 32),
                       bv);
                mma_f16(oacc[2 * p], ap, bv[0], bv[1]);
                mma_f16(oacc[2 * p + 1], ap, bv[2], bv[3]);
            }
        }
        __syncwarp();
        __syncthreads();
    }

    // epilogue: normalize + fp16 hi/lo split store
    const float il0 = 1.0f / sl0, il1 = 1.0f / sl1;
    const int row0 = q0 + lr;
    const int b_ = bh >> 4, h = bh & 15;
    const size_t o0 = ((size_t)b_ * Sn + row0) * Dn + h * DKn;
    const size_t o1 = o0 + (size_t)8 * Dn;
#pragma unroll
    for (int nf = 0; nf < 8; ++nf) {
        const int col = nf * 8 + tig * 2;
        float v0 = oacc[nf][0] * il0, v1 = oacc[nf][1] * il0;
        float v2 = oacc[nf][2] * il1, v3 = oacc[nf][3] * il1;
        __half h0 = __float2half_rn(v0), h1 = __float2half_rn(v1);
        __half h2 = __float2half_rn(v2), h3 = __float2half_rn(v3);
        __half2 hv0(h0, h1), hv1(h2, h3);
        __half2 lv0(__float2half_rn(v0 - __half2float(h0)),
                    __float2half_rn(v1 - __half2float(h1)));
        __half2 lv1(__float2half_rn(v2 - __half2float(h2)),
                    __float2half_rn(v3 - __half2float(h3)));
        *(uint32_t*)(Oh + o0 + col) = *(uint32_t*)&hv0;
        *(uint32_t*)(Ol + o0 + col) = *(uint32_t*)&lv0;
        *(uint32_t*)(Oh + o1 + col) = *(uint32_t*)&hv1;
        *(uint32_t*)(Ol + o1 + col) = *(uint32_t*)&lv1;
    }
}

// ---------------------------------------------------------------------------
extern "C" void kernel_launch(void* const* d_in, const int* in_sizes, int n_in,
                              void* d_out, int out_size) {
    const float* x  = (const float*)d_in[0];
    const float* Wq = (const float*)d_in[1];
    const float* Wk = (const float*)d_in[2];
    const float* Wv = (const float*)d_in[3];
    const float* Wo = (const float*)d_in[4];
    const int* pos  = (const int*)d_in[5];

    __half *pxh, *pxl, *pWh, *pQ, *pK, *pV, *pah, *pal;
    cudaGetSymbolAddress((void**)&pxh, g_xh);
    cudaGetSymbolAddress((void**)&pxl, g_xl);
    cudaGetSymbolAddress((void**)&pWh, g_Wh);
    cudaGetSymbolAddress((void**)&pQ, g_Q);
    cudaGetSymbolAddress((void**)&pK, g_K);
    cudaGetSymbolAddress((void**)&pV, g_V);
    cudaGetSymbolAddress((void**)&pah, g_ah);
    cudaGetSymbolAddress((void**)&pal, g_al);

    cudaFuncSetAttribute((const void*)gemm_mma_kernel<0>,
                         cudaFuncAttributeMaxDynamicSharedMemorySize, GEMM_SMEM);
    cudaFuncSetAttribute((const void*)gemm_mma_kernel<1>,
                         cudaFuncAttributeMaxDynamicSharedMemorySize, GEMM_SMEM);
    cudaFuncSetAttribute((const void*)gemm_mma_kernel<2>,
                         cudaFuncAttributeMaxDynamicSharedMemorySize, GEMM_SMEM);
    cudaFuncSetAttribute((const void*)gemm_mma_kernel<3>,
                         cudaFuncAttributeMaxDynamicSharedMemorySize, GEMM_SMEM);
    cudaFuncSetAttribute((const void*)attn_tc_kernel,
                         cudaFuncAttributeMaxDynamicSharedMemorySize, ATTN_SMEM);

    rope_tab_kernel<<<(Sn * 32 + 255) / 256, 256>>>(pos);
    split_x_kernel<<<Mn * Dn / 1024, 256>>>(x, pxh, pxl);
    const float* Ws[4] = {Wq, Wk, Wv, Wo};
    for (int w = 0; w < 4; ++w)
        transpose_half_kernel<<<dim3(32, 32), dim3(32, 8)>>>(
            Ws[w], pWh + (size_t)w * Dn * Dn);

    dim3 gg(Dn / TN, Mn / TM);  // (8, 64)
    gemm_mma_kernel<0><<<gg, 256, GEMM_SMEM>>>(pxh, pxl, pWh, pQ);
    gemm_mma_kernel<3><<<gg, 256, GEMM_SMEM>>>(pxh, pxl, pWh + Dn * Dn, pK);
    gemm_mma_kernel<1><<<gg, 256, GEMM_SMEM>>>(pxh, pxl, pWh + 2 * Dn * Dn, pV);

    dim3 agrid(Sn / 128, Bn * Hn);  // (16, 64)
    attn_tc_kernel<<<agrid, 256, ATTN_SMEM>>>(pQ, pK, pV, pah, pal);

    gemm_mma_kernel<2><<<gg, 256, GEMM_SMEM>>>(pah, pal, pWh + 3 * Dn * Dn,
                                               d_out);
}

// round 7
// speedup vs baseline: 4.5974x; 1.2776x over previous
#include <cuda_runtime.h>
#include <cuda_fp16.h>
#include <math.h>
#include <cstdint>

// Problem constants
constexpr int Bn = 4;
constexpr int Sn = 2048;
constexpr int Dn = 1024;
constexpr int Hn = 16;
constexpr int DKn = 64;
constexpr int Mn = Bn * Sn;  // 8192

// Q pre-scale: 1/sqrt(64) * log2(e)
#define QSCALE 0.18033688011112042f

// ---------------------------------------------------------------------------
// Scratch (static device arrays — no allocation allowed)
// ---------------------------------------------------------------------------
__device__ __half g_xh[Mn * Dn];          // x split hi
__device__ __half g_xl[Mn * Dn];          // x split lo
__device__ __half g_Wh[4 * Dn * Dn];      // W^T fp16 (4 weights, [n][k])
__device__ __half g_Q[Mn * Dn];           // [b,h,s,dk] fp16, scaled+RoPE
__device__ __half g_K[Mn * Dn];           // fp16, RoPE
__device__ __half g_V[Mn * Dn];           // fp16
__device__ __half g_ah[Mn * Dn];          // attn out fp16 [b,s,d]
__device__ float g_cos[Sn * 32];
__device__ float g_sin[Sn * 32];

// ---------------------------------------------------------------------------
// PTX helpers
// ---------------------------------------------------------------------------
__device__ __forceinline__ uint32_t s2u(const void* p) {
    uint32_t a;
    asm("{ .reg .u64 t; cvta.to.shared.u64 t, %1; cvt.u32.u64 %0, t; }"
        : "=r"(a) : "l"(p));
    return a;
}

__device__ __forceinline__ void cpa16(uint32_t dst, const void* src) {
    asm volatile("cp.async.cg.shared.global [%0], [%1], 16;"
                 :: "r"(dst), "l"(src) : "memory");
}
#define CP_COMMIT() asm volatile("cp.async.commit_group;" ::: "memory")
#define CP_WAIT1() asm volatile("cp.async.wait_group 1;" ::: "memory")
#define CP_WAIT0() asm volatile("cp.async.wait_group 0;" ::: "memory")

__device__ __forceinline__ void ldsm4(uint32_t addr, uint32_t* r) {
    asm volatile(
        "ldmatrix.sync.aligned.m8n8.x4.shared.b16 {%0,%1,%2,%3}, [%4];"
        : "=r"(r[0]), "=r"(r[1]), "=r"(r[2]), "=r"(r[3]) : "r"(addr));
}

__device__ __forceinline__ void ldsm4t(uint32_t addr, uint32_t* r) {
    asm volatile(
        "ldmatrix.sync.aligned.m8n8.x4.trans.shared.b16 {%0,%1,%2,%3}, [%4];"
        : "=r"(r[0]), "=r"(r[1]), "=r"(r[2]), "=r"(r[3]) : "r"(addr));
}

__device__ __forceinline__ void mma_f16(float* c, const uint32_t* a,
                                        uint32_t b0, uint32_t b1) {
    asm volatile(
        "mma.sync.aligned.m16n8k16.row.col.f32.f16.f16.f32 "
        "{%0,%1,%2,%3}, {%4,%5,%6,%7}, {%8,%9}, {%0,%1,%2,%3};"
        : "+f"(c[0]), "+f"(c[1]), "+f"(c[2]), "+f"(c[3])
        : "r"(a[0]), "r"(a[1]), "r"(a[2]), "r"(a[3]), "r"(b0), "r"(b1));
}

// Fast exp2 on the FMA pipe (input <= 0); ~4e-5 rel err.
__device__ __forceinline__ float exp2_fast(float y) {
    y = fmaxf(y, -126.0f);
    float fe = y + 12582912.0f;
    int ei = __float_as_int(fe) << 23;
    float fr = y - (fe - 12582912.0f);
    float p = 0.0096181291f;
    p = fmaf(p, fr, 0.0555041087f);
    p = fmaf(p, fr, 0.2402264923f);
    p = fmaf(p, fr, 0.6931471806f);
    p = fmaf(p, fr, 1.0f);
    return __int_as_float(__float_as_int(p) + ei);
}

// ---------------------------------------------------------------------------
// Prep kernels
// ---------------------------------------------------------------------------
__global__ void rope_tab_kernel(const int* __restrict__ pos) {
    int idx = blockIdx.x * 256 + threadIdx.x;
    if (idx >= Sn * 32) return;
    int s = idx >> 5;
    int f = idx & 31;
    float inv = expf(-(float)f * (logf(10000.0f) / 32.0f));
    float a = (float)pos[s] * inv;
    g_cos[idx] = cosf(a);
    g_sin[idx] = sinf(a);
}

__global__ void split_x_kernel(const float* __restrict__ x,
                               __half* __restrict__ xh,
                               __half* __restrict__ xl) {
    size_t i = ((size_t)blockIdx.x * 256 + threadIdx.x) * 4;
    float4 a = *(const float4*)(x + i);
    float v[4] = {a.x, a.y, a.z, a.w};
    __half2 h2[2], l2[2];
#pragma unroll
    for (int p = 0; p < 2; ++p) {
        __half h0 = __float2half_rn(v[2 * p]);
        __half h1 = __float2half_rn(v[2 * p + 1]);
        h2[p] = __half2(h0, h1);
        l2[p] = __half2(__float2half_rn(v[2 * p] - __half2float(h0)),
                        __float2half_rn(v[2 * p + 1] - __half2float(h1)));
    }
    *(uint2*)(xh + i) = *(uint2*)h2;
    *(uint2*)(xl + i) = *(uint2*)l2;
}

// All four W[k][n] -> WT[n][k] fp16 in one launch (blockIdx.z = weight id)
__global__ void transpose_half_kernel(const float* __restrict__ W0,
                                      const float* __restrict__ W1,
                                      const float* __restrict__ W2,
                                      const float* __restrict__ W3,
                                      __half* __restrict__ Th) {
    __shared__ float t[32][33];
    const float* W = (blockIdx.z == 0) ? W0
                   : (blockIdx.z == 1) ? W1
                   : (blockIdx.z == 2) ? W2 : W3;
    __half* T = Th + (size_t)blockIdx.z * Dn * Dn;
    int n0 = blockIdx.x * 32, k0 = blockIdx.y * 32;
    int tx = threadIdx.x;
#pragma unroll
    for (int i = threadIdx.y; i < 32; i += 8)
        t[i][tx] = W[(size_t)(k0 + i) * Dn + n0 + tx];
    __syncthreads();
#pragma unroll
    for (int i = threadIdx.y; i < 32; i += 8)
        T[(size_t)(n0 + i) * Dn + k0 + tx] = __float2half_rn(t[tx][i]);
}

// ---------------------------------------------------------------------------
// Fused QKV GEMM (mma.sync fp16): out[8192, 3072] = x @ [Wq|Wk|Wv]^T
// Q,K: 2-pass hi/lo split on A;  V: single-pass.
// CTA 128x128, K-chunk 32, 2-stage cp.async pipeline, 3 smem planes.
// Epilogue per weight: w0 Q (RoPE+QSCALE), w1 K (RoPE), w2 V (plain);
// all head-major fp16.
// ---------------------------------------------------------------------------
constexpr int TM = 128, TN = 128, TK = 32;
constexpr int NCHUNK = Dn / TK;       // 32
constexpr int ROWB = 80;              // bytes per 32-half row (64B data + pad)
constexpr int PLANE = 128 * ROWB;     // 10240
constexpr int STAGE3 = 3 * PLANE;     // A_hi, A_lo, B
constexpr int QKV_SMEM = 2 * STAGE3;  // 61440
constexpr int STAGE2 = 2 * PLANE;     // A, B
constexpr int OUT_SMEM = 2 * STAGE2;  // 40960

__global__ __launch_bounds__(256) void gemm_qkv_kernel(
    const __half* __restrict__ Ah, const __half* __restrict__ Al,
    const __half* __restrict__ Wall, __half* __restrict__ Qo,
    __half* __restrict__ Ko, __half* __restrict__ Vo) {
    extern __shared__ char smem[];
    const uint32_t sb = s2u(smem);
    const int tid = threadIdx.x;
    const int wid = tid >> 5, lane = tid & 31;
    const int warp_m = wid & 3, warp_n = wid >> 2;
    const int m0 = blockIdx.y * TM;
    const int n0g = blockIdx.x * TN;          // 0..2944
    const int w = n0g >> 10;                  // weight id 0..2
    const int n0 = n0g & (Dn - 1);            // local n
    const bool twopass = (w < 2);
    const __half* Bw = Wall + (size_t)w * Dn * Dn;

    float acc[2][8][4];
#pragma unroll
    for (int mf = 0; mf < 2; ++mf)
#pragma unroll
        for (int nf = 0; nf < 8; ++nf)
#pragma unroll
            for (int j = 0; j < 4; ++j) acc[mf][nf][j] = 0.0f;

    const int lrow = lane & 15;
    const int lcol = (lane >> 4) * 16;
    const uint32_t aOff = (uint32_t)((warp_m * 32 + lrow) * ROWB + lcol);
    const uint32_t bOff = (uint32_t)(2 * PLANE + (warp_n * 64 + lrow) * ROWB + lcol);

    // stage loader: planes 0=Ah, 1=Al (skipped for V), 2=B
    auto load_stage = [&](uint32_t stb, int k0) {
#pragma unroll
        for (int i = 0; i < 6; ++i) {
            int op = tid + i * 256;
            int plane = op >> 9;
            int wv = op & 511;
            int r = wv >> 2, ch = wv & 3;
            uint32_t dst = stb + plane * PLANE + r * ROWB + ch * 16;
            if (plane == 0)
                cpa16(dst, Ah + (size_t)(m0 + r) * Dn + k0 + ch * 8);
            else if (plane == 1) {
                if (twopass)
                    cpa16(dst, Al + (size_t)(m0 + r) * Dn + k0 + ch * 8);
            } else
                cpa16(dst, Bw + (size_t)(n0 + r) * Dn + k0 + ch * 8);
        }
    };

    load_stage(sb, 0);
    CP_COMMIT();

    for (int c = 0; c < NCHUNK; ++c) {
        if (c + 1 < NCHUNK) {
            load_stage(sb + ((c + 1) & 1) * STAGE3, (c + 1) * TK);
            CP_COMMIT();
            CP_WAIT1();
        } else {
            CP_WAIT0();
        }
        __syncthreads();

        const uint32_t stb = sb + (c & 1) * STAGE3;
#pragma unroll
        for (int ks = 0; ks < 2; ++ks) {
            const uint32_t kb = ks * 32;
            uint32_t ah[2][4], al[2][4];
            ldsm4(stb + aOff + kb, ah[0]);
            ldsm4(stb + aOff + 16 * ROWB + kb, ah[1]);
            if (twopass) {
                ldsm4(stb + PLANE + aOff + kb, al[0]);
                ldsm4(stb + PLANE + aOff + 16 * ROWB + kb, al[1]);
            }
            uint32_t bf[4][4];
#pragma unroll
            for (int p = 0; p < 4; ++p)
                ldsm4(stb + bOff + p * 16 * ROWB + kb, bf[p]);
#pragma unroll
            for (int mf = 0; mf < 2; ++mf)
#pragma unroll
                for (int nf = 0; nf < 8; ++nf) {
                    const int pr = nf >> 1, wh = nf & 1;
                    mma_f16(acc[mf][nf], ah[mf], bf[pr][wh], bf[pr][2 + wh]);
                    if (twopass)
                        mma_f16(acc[mf][nf], al[mf], bf[pr][wh], bf[pr][2 + wh]);
                }
        }
        __syncthreads();
    }

    // Epilogue: head-major fp16 with per-weight transform
    __half* out = (w == 0) ? Qo : (w == 1) ? Ko : Vo;
    const int gid = lane >> 2, tig = lane & 3;
#pragma unroll
    for (int mf = 0; mf < 2; ++mf)
#pragma unroll
        for (int nf = 0; nf < 8; ++nf) {
            const float* cc = acc[mf][nf];
            const int row0 = m0 + warp_m * 32 + mf * 16 + gid;
            const int dcol = nf * 8 + tig * 2;
            const int h = (n0 + warp_n * 64) >> 6;
#pragma unroll
            for (int rr = 0; rr < 2; ++rr) {
                const int row = row0 + rr * 8;
                const int b_ = row >> 11, s_ = row & (Sn - 1);
                float e0 = cc[rr * 2], e1 = cc[rr * 2 + 1];
                if (w < 2) {
                    const int f = nf * 4 + tig;
                    const float cz = g_cos[s_ * 32 + f];
                    const float sz = g_sin[s_ * 32 + f];
                    const float r1 = e0 * cz - e1 * sz;
                    const float r2 = e0 * sz + e1 * cz;
                    e0 = r1; e1 = r2;
                }
                if (w == 0) { e0 *= QSCALE; e1 *= QSCALE; }
                __half2 hv(__float2half_rn(e0), __float2half_rn(e1));
                *(uint32_t*)(out + (((size_t)b_ * Hn + h) * Sn + s_) * DKn +
                             dcol) = *(uint32_t*)&hv;
            }
        }
}

// ---------------------------------------------------------------------------
// Output projection GEMM (single-pass fp16): out[8192,1024] = a @ Wo^T, fp32.
// ---------------------------------------------------------------------------
__global__ __launch_bounds__(256) void gemm_out_kernel(
    const __half* __restrict__ A, const __half* __restrict__ Bw,
    float* __restrict__ out) {
    extern __shared__ char smem[];
    const uint32_t sb = s2u(smem);
    const int tid = threadIdx.x;
    const int wid = tid >> 5, lane = tid & 31;
    const int warp_m = wid & 3, warp_n = wid >> 2;
    const int m0 = blockIdx.y * TM, n0 = blockIdx.x * TN;

    float acc[2][8][4];
#pragma unroll
    for (int mf = 0; mf < 2; ++mf)
#pragma unroll
        for (int nf = 0; nf < 8; ++nf)
#pragma unroll
            for (int j = 0; j < 4; ++j) acc[mf][nf][j] = 0.0f;

    const int lrow = lane & 15;
    const int lcol = (lane >> 4) * 16;
    const uint32_t aOff = (uint32_t)((warp_m * 32 + lrow) * ROWB + lcol);
    const uint32_t bOff = (uint32_t)(PLANE + (warp_n * 64 + lrow) * ROWB + lcol);

    auto load_stage = [&](uint32_t stb, int k0) {
#pragma unroll
        for (int i = 0; i < 4; ++i) {
            int op = tid + i * 256;
            int plane = op >> 9;
            int wv = op & 511;
            int r = wv >> 2, ch = wv & 3;
            uint32_t dst = stb + plane * PLANE + r * ROWB + ch * 16;
            if (plane == 0)
                cpa16(dst, A + (size_t)(m0 + r) * Dn + k0 + ch * 8);
            else
                cpa16(dst, Bw + (size_t)(n0 + r) * Dn + k0 + ch * 8);
        }
    };

    load_stage(sb, 0);
    CP_COMMIT();

    for (int c = 0; c < NCHUNK; ++c) {
        if (c + 1 < NCHUNK) {
            load_stage(sb + ((c + 1) & 1) * STAGE2, (c + 1) * TK);
            CP_COMMIT();
            CP_WAIT1();
        } else {
            CP_WAIT0();
        }
        __syncthreads();

        const uint32_t stb = sb + (c & 1) * STAGE2;
#pragma unroll
        for (int ks = 0; ks < 2; ++ks) {
            const uint32_t kb = ks * 32;
            uint32_t ah[2][4];
            ldsm4(stb + aOff + kb, ah[0]);
            ldsm4(stb + aOff + 16 * ROWB + kb, ah[1]);
            uint32_t bf[4][4];
#pragma unroll
            for (int p = 0; p < 4; ++p)
                ldsm4(stb + bOff + p * 16 * ROWB + kb, bf[p]);
#pragma unroll
            for (int mf = 0; mf < 2; ++mf)
#pragma unroll
                for (int nf = 0; nf < 8; ++nf) {
                    const int pr = nf >> 1, wh = nf & 1;
                    mma_f16(acc[mf][nf], ah[mf], bf[pr][wh], bf[pr][2 + wh]);
                }
        }
        __syncthreads();
    }

    const int gid = lane >> 2, tig = lane & 3;
#pragma unroll
    for (int mf = 0; mf < 2; ++mf)
#pragma unroll
        for (int nf = 0; nf < 8; ++nf) {
            const float* cc = acc[mf][nf];
            const int row0 = m0 + warp_m * 32 + mf * 16 + gid;
            const int col = n0 + warp_n * 64 + nf * 8 + tig * 2;
            *(float2*)(out + (size_t)row0 * Dn + col) = make_float2(cc[0], cc[1]);
            *(float2*)(out + (size_t)(row0 + 8) * Dn + col) =
                make_float2(cc[2], cc[3]);
        }
}

// ---------------------------------------------------------------------------
// Flash attention, fp16 mma + FFMA exp2. (identical math to R6; fp16-only out)
// ---------------------------------------------------------------------------
constexpr int KVSB = 144;
constexpr int KVPLANE = 64 * KVSB;
constexpr int STAGE_B = 2 * KVPLANE;
constexpr int P_OFF = 2 * STAGE_B;
constexpr int ATTN_SMEM = P_OFF + 8 * 16 * KVSB;  // 55296 B

__device__ __forceinline__ void load_kv(uint32_t dstb,
                                        const __half* __restrict__ Kb,
                                        const __half* __restrict__ Vb, int kt,
                                        int tid) {
    const __half* s0 = Kb + (size_t)kt * 64 * 64;
    const __half* s1 = Vb + (size_t)kt * 64 * 64;
#pragma unroll
    for (int i = 0; i < 4; ++i) {
        int idx = tid + i * 256;
        int t = idx >> 9;
        int w = idx & 511;
        int r = w >> 3, ch = w & 7;
        uint32_t d = dstb + (uint32_t)(t * KVPLANE + r * KVSB + ch * 16);
        const __half* s = (t ? s1 : s0) + r * 64 + ch * 8;
        cpa16(d, s);
    }
}

__global__ __launch_bounds__(256, 2) void attn_tc_kernel(
    const __half* __restrict__ Q, const __half* __restrict__ K,
    const __half* __restrict__ V, __half* __restrict__ Oh) {
    extern __shared__ char smc[];
    const uint32_t smb = s2u(smc);
    const int tid = threadIdx.x;
    const int wid = tid >> 5, lane = tid & 31;
    const int gid = lane >> 2, tig = lane & 3;
    const int bh = blockIdx.y;
    const int qt = (int)gridDim.x - 1 - (int)blockIdx.x;
    const int q0 = qt * 128;

    const __half* Qb = Q + ((size_t)bh * Sn + q0) * DKn;
    const __half* Kb = K + (size_t)bh * Sn * DKn;
    const __half* Vb = V + (size_t)bh * Sn * DKn;

    const int lr = wid * 16 + gid;
    uint32_t aq[4][4];
#pragma unroll
    for (int kf = 0; kf < 4; ++kf) {
        const __half* p = Qb + (size_t)lr * DKn + kf * 16 + tig * 2;
        aq[kf][0] = *(const uint32_t*)(p);
        aq[kf][1] = *(const uint32_t*)(p + 8 * DKn);
        aq[kf][2] = *(const uint32_t*)(p + 8);
        aq[kf][3] = *(const uint32_t*)(p + 8 * DKn + 8);
    }

    float oacc[8][4];
#pragma unroll
    for (int nf = 0; nf < 8; ++nf)
#pragma unroll
        for (int j = 0; j < 4; ++j) oacc[nf][j] = 0.0f;
    float mr0 = -1e30f, mr1 = -1e30f, sl0 = 0.0f, sl1 = 0.0f;

    const int nkt = 2 * qt + 2;
    load_kv(smb, Kb, Vb, 0, tid);
    CP_COMMIT();

    const int lrow = lane & 15;
    const uint32_t kOffBase = (uint32_t)(lrow * KVSB + (lane >> 4) * 16);
    const uint32_t pOff = (uint32_t)(P_OFF + wid * 16 * KVSB + lrow * KVSB +
                                     (lane >> 4) * 16);
    const uint32_t vOffBase = (uint32_t)(lrow * KVSB + (lane >> 4) * 16);

    for (int kt = 0; kt < nkt; ++kt) {
        if (kt + 1 < nkt) {
            load_kv(smb + ((kt + 1) & 1) * STAGE_B, Kb, Vb, kt + 1, tid);
            CP_COMMIT();
            CP_WAIT1();
        } else {
            CP_WAIT0();
        }
        __syncthreads();
        const uint32_t Ks = smb + (kt & 1) * STAGE_B;
        const uint32_t Vs = Ks + KVPLANE;

        float sacc[8][4];
#pragma unroll
        for (int nf = 0; nf < 8; ++nf)
#pragma unroll
            for (int j = 0; j < 4; ++j) sacc[nf][j] = 0.0f;
#pragma unroll
        for (int kf = 0; kf < 4; ++kf) {
            uint32_t bk[4][4];
#pragma unroll
            for (int p = 0; p < 4; ++p)
                ldsm4(Ks + kOffBase + p * 16 * KVSB + kf * 32, bk[p]);
#pragma unroll
            for (int p = 0; p < 4; ++p) {
                mma_f16(sacc[2 * p], aq[kf], bk[p][0], bk[p][2]);
                mma_f16(sacc[2 * p + 1], aq[kf], bk[p][1], bk[p][3]);
            }
        }

        if (kt >= 2 * qt) {
            const int cb = kt * 64 + tig * 2;
            const int r0g = q0 + lr;
#pragma unroll
            for (int nf = 0; nf < 8; ++nf) {
                const int c0 = cb + nf * 8;
                if (c0 > r0g) sacc[nf][0] = -1e30f;
                if (c0 + 1 > r0g) sacc[nf][1] = -1e30f;
                if (c0 > r0g + 8) sacc[nf][2] = -1e30f;
                if (c0 + 1 > r0g + 8) sacc[nf][3] = -1e30f;
            }
        }

        float t0 = -1e30f, t1 = -1e30f;
#pragma unroll
        for (int nf = 0; nf < 8; ++nf) {
            t0 = fmaxf(t0, fmaxf(sacc[nf][0], sacc[nf][1]));
            t1 = fmaxf(t1, fmaxf(sacc[nf][2], sacc[nf][3]));
        }
        t0 = fmaxf(t0, __shfl_xor_sync(0xffffffffu, t0, 1));
        t0 = fmaxf(t0, __shfl_xor_sync(0xffffffffu, t0, 2));
        t1 = fmaxf(t1, __shfl_xor_sync(0xffffffffu, t1, 1));
        t1 = fmaxf(t1, __shfl_xor_sync(0xffffffffu, t1, 2));
        const float nm0 = fmaxf(mr0, t0), nm1 = fmaxf(mr1, t1);
        const float cr0 = exp2_fast(mr0 - nm0), cr1 = exp2_fast(mr1 - nm1);
        mr0 = nm0; mr1 = nm1;
        float s0 = 0.0f, s1 = 0.0f;
#pragma unroll
        for (int nf = 0; nf < 8; ++nf) {
            sacc[nf][0] = exp2_fast(sacc[nf][0] - nm0);
            sacc[nf][1] = exp2_fast(sacc[nf][1] - nm0);
            sacc[nf][2] = exp2_fast(sacc[nf][2] - nm1);
            sacc[nf][3] = exp2_fast(sacc[nf][3] - nm1);
            s0 += sacc[nf][0] + sacc[nf][1];
            s1 += sacc[nf][2] + sacc[nf][3];
        }
        s0 += __shfl_xor_sync(0xffffffffu, s0, 1);
        s0 += __shfl_xor_sync(0xffffffffu, s0, 2);
        s1 += __shfl_xor_sync(0xffffffffu, s1, 1);
        s1 += __shfl_xor_sync(0xffffffffu, s1, 2);
        sl0 = sl0 * cr0 + s0;
        sl1 = sl1 * cr1 + s1;
#pragma unroll
        for (int nf = 0; nf < 8; ++nf) {
            oacc[nf][0] *= cr0;
            oacc[nf][1] *= cr0;
            oacc[nf][2] *= cr1;
            oacc[nf][3] *= cr1;
        }

        {
            char* Pw = smc + (P_OFF + wid * 16 * KVSB);
#pragma unroll
            for (int nf = 0; nf < 8; ++nf) {
                const int cc = nf * 8 + tig * 2;
                __half2 p0(__float2half_rn(sacc[nf][0]),
                           __float2half_rn(sacc[nf][1]));
                __half2 p1(__float2half_rn(sacc[nf][2]),
                           __float2half_rn(sacc[nf][3]));
                *(uint32_t*)(Pw + gid * KVSB + cc * 2) = *(uint32_t*)&p0;
                *(uint32_t*)(Pw + (gid + 8) * KVSB + cc * 2) = *(uint32_t*)&p1;
            }
        }
        __syncwarp();

#pragma unroll
        for (int kf = 0; kf < 4; ++kf) {
            uint32_t ap[4];
            ldsm4(smb + pOff + kf * 32, ap);
#pragma unroll
            for (int p = 0; p < 4; ++p) {
                uint32_t bv[4];
                ldsm4t(Vs + (uint32_t)(kf * 16 * KVSB) + vOffBase +
                           (uint32_t)(p * 32),
                       bv);
                mma_f16(oacc[2 * p], ap, bv[0], bv[1]);
                mma_f16(oacc[2 * p + 1], ap, bv[2], bv[3]);
            }
        }
        __syncwarp();
        __syncthreads();
    }

    const float il0 = 1.0f / sl0, il1 = 1.0f / sl1;
    const int row0 = q0 + lr;
    const int b_ = bh >> 4, h = bh & 15;
    const size_t o0 = ((size_t)b_ * Sn + row0) * Dn + h * DKn;
    const size_t o1 = o0 + (size_t)8 * Dn;
#pragma unroll
    for (int nf = 0; nf < 8; ++nf) {
        const int col = nf * 8 + tig * 2;
        __half2 hv0(__float2half_rn(oacc[nf][0] * il0),
                    __float2half_rn(oacc[nf][1] * il0));
        __half2 hv1(__float2half_rn(oacc[nf][2] * il1),
                    __float2half_rn(oacc[nf][3] * il1));
        *(uint32_t*)(Oh + o0 + col) = *(uint32_t*)&hv0;
        *(uint32_t*)(Oh + o1 + col) = *(uint32_t*)&hv1;
    }
}

// ---------------------------------------------------------------------------
extern "C" void kernel_launch(void* const* d_in, const int* in_sizes, int n_in,
                              void* d_out, int out_size) {
    const float* x  = (const float*)d_in[0];
    const float* Wq = (const float*)d_in[1];
    const float* Wk = (const float*)d_in[2];
    const float* Wv = (const float*)d_in[3];
    const float* Wo = (const float*)d_in[4];
    const int* pos  = (const int*)d_in[5];

    __half *pxh, *pxl, *pWh, *pQ, *pK, *pV, *pah;
    cudaGetSymbolAddress((void**)&pxh, g_xh);
    cudaGetSymbolAddress((void**)&pxl, g_xl);
    cudaGetSymbolAddress((void**)&pWh, g_Wh);
    cudaGetSymbolAddress((void**)&pQ, g_Q);
    cudaGetSymbolAddress((void**)&pK, g_K);
    cudaGetSymbolAddress((void**)&pV, g_V);
    cudaGetSymbolAddress((void**)&pah, g_ah);

    cudaFuncSetAttribute((const void*)gemm_qkv_kernel,
                         cudaFuncAttributeMaxDynamicSharedMemorySize, QKV_SMEM);
    cudaFuncSetAttribute((const void*)gemm_out_kernel,
                         cudaFuncAttributeMaxDynamicSharedMemorySize, OUT_SMEM);
    cudaFuncSetAttribute((const void*)attn_tc_kernel,
                         cudaFuncAttributeMaxDynamicSharedMemorySize, ATTN_SMEM);

    rope_tab_kernel<<<(Sn * 32 + 255) / 256, 256>>>(pos);
    split_x_kernel<<<Mn * Dn / 1024, 256>>>(x, pxh, pxl);
    transpose_half_kernel<<<dim3(32, 32, 4), dim3(32, 8)>>>(Wq, Wk, Wv, Wo, pWh);

    dim3 gqkv(3 * Dn / TN, Mn / TM);  // (24, 64)
    gemm_qkv_kernel<<<gqkv, 256, QKV_SMEM>>>(pxh, pxl, pWh, pQ, pK, pV);

    dim3 agrid(Sn / 128, Bn * Hn);  // (16, 64)
    attn_tc_kernel<<<agrid, 256, ATTN_SMEM>>>(pQ, pK, pV, pah);

    dim3 gout(Dn / TN, Mn / TM);  // (8, 64)
    gemm_out_kernel<<<gout, 256, OUT_SMEM>>>(pah, pWh + 3 * (size_t)Dn * Dn,
                                             (float*)d_out);
}